// round 13
// baseline (speedup 1.0000x reference)
#include <cuda_runtime.h>
#include <cuda_fp16.h>
#include <math.h>
#include <stdint.h>

// Problem dims (fixed by reference)
#define NB 4
#define NT 2048
#define NC 2048
#define NH 16
#define ND 128
#define NBH (NB*NH)          // 64
#define M1 (NB*NT)           // 8192
#define KDIM 2048

// ---------------------------------------------------------------------------
// Device scratch (allocation-free rule: __device__ globals)
// ---------------------------------------------------------------------------
__device__ __align__(256) float g_q[16777216];   // [B*H][T][D] fp32 (pre-rope)
__device__ __align__(256) float g_k[16777216];
__device__ __align__(256) float g_v[16777216];

__device__ __align__(256) __half g_xh[16777216];    // x fp16     [8192][2048]
__device__ __align__(256) __half g_Wh[12582912];    // Wqkv^T     [6144][2048]
__device__ __align__(256) __half g_Woh[4194304];    // Wo^T       [2048][2048]
__device__ __align__(256) __half g_attf[16777216];  // att fp16   [8192][2048]

__device__ __align__(256) __half g_qh[16777216];    // rope'd q fp16 [bh][t][d]
__device__ __align__(256) __half g_kh[16777216];    // rope'd k fp16 [bh][t][d]
__device__ __align__(256) __half g_vT[16777216];    // v^T fp16      [bh][d][t]

// ---------------------------------------------------------------------------
// PTX helpers (Ampere-class, valid under compute_103)
// ---------------------------------------------------------------------------
__device__ __forceinline__ uint32_t smem_u32(const void* p) {
    uint32_t a;
    asm("{ .reg .u64 t; cvta.to.shared.u64 t, %1; cvt.u32.u64 %0, t; }"
        : "=r"(a) : "l"(p));
    return a;
}
__device__ __forceinline__ void cp16(uint32_t s, const void* g) {
    asm volatile("cp.async.cg.shared.global [%0], [%1], 16;" :: "r"(s), "l"(g));
}
__device__ __forceinline__ void ldm4(uint32_t* r, uint32_t addr) {
    asm volatile("ldmatrix.sync.aligned.m8n8.x4.shared.b16 {%0,%1,%2,%3}, [%4];"
                 : "=r"(r[0]), "=r"(r[1]), "=r"(r[2]), "=r"(r[3]) : "r"(addr));
}
__device__ __forceinline__ void mma_f16(float* c, const uint32_t* a, const uint32_t* b) {
    asm volatile(
        "mma.sync.aligned.m16n8k16.row.col.f32.f16.f16.f32 "
        "{%0,%1,%2,%3}, {%4,%5,%6,%7}, {%8,%9}, {%0,%1,%2,%3};"
        : "+f"(c[0]), "+f"(c[1]), "+f"(c[2]), "+f"(c[3])
        : "r"(a[0]), "r"(a[1]), "r"(a[2]), "r"(a[3]), "r"(b[0]), "r"(b[1]));
}
__device__ __forceinline__ float ex2(float x) {
    float y; asm("ex2.approx.f32 %0, %1;" : "=f"(y) : "f"(x)); return y;
}
__device__ __forceinline__ uint32_t packh(float x, float y) {
    __half2 h = __floats2half2_rn(x, y);
    return *(uint32_t*)&h;
}

// ---------------------------------------------------------------------------
// Plain fp16 mma.sync GEMM: C[M,N] = A[M,K] @ B^T
// BM=128 BN=256 BK=64, 8 warps (2x4), warp tile 64x64 (LDSM:MMA = 1:4).
// 3-stage pipeline, one sync per stage, 144KB smem, 1 CTA/SM.
// ---------------------------------------------------------------------------
#define BK 64
#define NKCH (KDIM/BK)       // 32
#define STG_SZ 49152         // A 16KB | B 32KB
#define GEMM_SMEM (3*STG_SZ) // 147456

__device__ __forceinline__ void load_stage48(
    uint32_t stg, int t, int koff,
    const __half* pA, const __half* pB)
{
    #pragma unroll
    for (int i = 0; i < 4; ++i) {      // A: 128 rows x 8 chunks
        int idx = t + i * 256;
        int r = idx >> 3, ci = idx & 7;
        uint32_t so = stg + r * 128 + ((ci ^ (r & 7)) << 4);
        cp16(so, pA + (size_t)r * KDIM + koff + ci * 8);
    }
    #pragma unroll
    for (int i = 0; i < 8; ++i) {      // B: 256 rows x 8 chunks
        int idx = t + i * 256;
        int r = idx >> 3, ci = idx & 7;
        uint32_t so = stg + 16384 + r * 128 + ((ci ^ (r & 7)) << 4);
        cp16(so, pB + (size_t)r * KDIM + koff + ci * 8);
    }
    asm volatile("cp.async.commit_group;" ::: "memory");
}

__device__ __forceinline__ void compute_stage(
    uint32_t stg, int wm, int wn, int lane, float acc[4][8][4])
{
    const int r = lane & 7, g = lane >> 3;
    const uint32_t rx = (uint32_t)r << 4;
    const uint32_t baseA = stg + (uint32_t)(wm * 64 + (g & 1) * 8 + r) * 128;
    const uint32_t hA4   = (uint32_t)(g >> 1) << 4;
    const uint32_t baseB = stg + 16384 + (uint32_t)(wn * 64 + (g >> 1) * 8 + r) * 128;
    const uint32_t hB4   = (uint32_t)(g & 1) << 4;

    #pragma unroll
    for (int s = 0; s < 4; ++s) {
        const uint32_t offA = (((uint32_t)s << 5) | hA4) ^ rx;
        const uint32_t offB = (((uint32_t)s << 5) | hB4) ^ rx;
        uint32_t ah[4][4], bh[4][4];
        #pragma unroll
        for (int i = 0; i < 4; ++i)
            ldm4(ah[i], baseA + i * 2048 + offA);
        #pragma unroll
        for (int j = 0; j < 4; ++j)
            ldm4(bh[j], baseB + j * 2048 + offB);
        #pragma unroll
        for (int i = 0; i < 4; ++i)
            #pragma unroll
            for (int j = 0; j < 4; ++j) {
                mma_f16(acc[i][2*j],   ah[i], &bh[j][0]);
                mma_f16(acc[i][2*j+1], ah[i], &bh[j][2]);
            }
    }
}

template<int EPI>
__global__ __launch_bounds__(256, 1)
void gemm_fp16(const __half* __restrict__ A, const __half* __restrict__ B,
               const float* __restrict__ bias, float* __restrict__ C)
{
    extern __shared__ __align__(1024) char smbuf[];
    uint32_t sb = smem_u32(smbuf);
    const int t    = threadIdx.x;
    const int lane = t & 31, wid = t >> 5;
    const int wm   = wid >> 2, wn = wid & 3;
    const int m0   = blockIdx.y * 128;
    const int n0   = blockIdx.x * 256;

    float acc[4][8][4];
    #pragma unroll
    for (int i = 0; i < 4; ++i)
        #pragma unroll
        for (int q = 0; q < 8; ++q)
            #pragma unroll
            for (int k = 0; k < 4; ++k) acc[i][q][k] = 0.f;

    const __half* pA = A + (size_t)m0 * KDIM;
    const __half* pB = B + (size_t)n0 * KDIM;

    load_stage48(sb,          t, 0,  pA, pB);
    load_stage48(sb + STG_SZ, t, BK, pA, pB);

    int bc = 0, bl2 = 2;   // rotating buffers: kt%3, (kt+2)%3
    #pragma unroll 1
    for (int kt = 0; kt < NKCH; ++kt) {
        if (kt == NKCH - 1) asm volatile("cp.async.wait_group 0;" ::: "memory");
        else                asm volatile("cp.async.wait_group 1;" ::: "memory");
        __syncthreads();
        if (kt + 2 < NKCH)
            load_stage48(sb + bl2 * STG_SZ, t, (kt + 2) * BK, pA, pB);
        compute_stage(sb + bc * STG_SZ, wm, wn, lane, acc);
        bc  = (bc  == 2) ? 0 : bc  + 1;
        bl2 = (bl2 == 2) ? 0 : bl2 + 1;
    }

    const int mr  = (lane >> 2);
    const int nc0 = (lane & 3) * 2;
    if (EPI == 0) {
        const int b = m0 >> 11;
        #pragma unroll
        for (int i = 0; i < 4; ++i) {
            const int m  = m0 + wm * 64 + i * 16 + mr;
            const int tq = m & 2047;
            #pragma unroll
            for (int q = 0; q < 8; ++q) {
                const int n = n0 + wn * 64 + q * 8 + nc0;
                const int which = n >> 11;
                const int h     = (n >> 7) & 15;
                const int d     = n & 127;
                float* dst = (which == 0) ? (float*)g_q
                           : (which == 1) ? (float*)g_k : (float*)g_v;
                float2 bs = *(const float2*)&bias[n];
                size_t off = ((size_t)(b * 16 + h) * NT + tq) * ND + d;
                float2 v0, v1;
                v0.x = acc[i][q][0] + bs.x;  v0.y = acc[i][q][1] + bs.y;
                v1.x = acc[i][q][2] + bs.x;  v1.y = acc[i][q][3] + bs.y;
                *(float2*)&dst[off]          = v0;
                *(float2*)&dst[off + 8 * ND] = v1;
            }
        }
    } else {
        #pragma unroll
        for (int i = 0; i < 4; ++i) {
            const int m = m0 + wm * 64 + i * 16 + mr;
            #pragma unroll
            for (int q = 0; q < 8; ++q) {
                const int n = n0 + wn * 64 + q * 8 + nc0;
                float2 bs = *(const float2*)&bias[n];
                float2 v0, v1;
                v0.x = acc[i][q][0] + bs.x;  v0.y = acc[i][q][1] + bs.y;
                v1.x = acc[i][q][2] + bs.x;  v1.y = acc[i][q][3] + bs.y;
                *(float2*)&C[(size_t)m * NC + n]       = v0;
                *(float2*)&C[(size_t)(m + 8) * NC + n] = v1;
            }
        }
    }
}

// ---------------------------------------------------------------------------
// fp32 -> fp16 convert (x input)
// ---------------------------------------------------------------------------
__global__ void conv_f16_kernel(const float* __restrict__ in,
                                __half* __restrict__ out, int n4)
{
    int i = blockIdx.x * blockDim.x + threadIdx.x;
    if (i >= n4) return;
    float4 v = ((const float4*)in)[i];
    uint32_t* op = (uint32_t*)out;
    op[2 * i]     = packh(v.x, v.y);
    op[2 * i + 1] = packh(v.z, v.w);
}

// ---------------------------------------------------------------------------
// fp32 [K][N] -> transposed fp16 [N][K]  (weights)
// ---------------------------------------------------------------------------
__global__ void transpose_conv_kernel(const float* __restrict__ in,
                                      __half* __restrict__ out,
                                      int K, int N)
{
    __shared__ float tile[32][33];
    const int n0 = blockIdx.x * 32, k0 = blockIdx.y * 32;
    const int tx = threadIdx.x, ty = threadIdx.y;
    #pragma unroll
    for (int i = 0; i < 32; i += 8)
        tile[ty + i][tx] = in[(size_t)(k0 + ty + i) * N + n0 + tx];
    __syncthreads();
    #pragma unroll
    for (int i = 0; i < 32; i += 8) {
        size_t o = (size_t)(n0 + ty + i) * K + k0 + tx;
        out[o] = __float2half_rn(tile[tx][ty + i]);
    }
}

// ---------------------------------------------------------------------------
// RoPE fused with fp16 conversion: q and k -> plain fp16 (same path)
// ---------------------------------------------------------------------------
__global__ void rope_conv_kernel()
{
    const int PER = NBH * NT * 32;  // 4194304
    int idx = blockIdx.x * blockDim.x + threadIdx.x;
    const bool isK = idx >= PER;
    int r = isK ? idx - PER : idx;
    const float* src = isK ? (const float*)g_k : (const float*)g_q;
    __half* dst = isK ? (__half*)g_kh : (__half*)g_qh;
    int fi   = r & 31;
    int tpos = (r >> 5) & (NT - 1);
    int bh   = r >> 16;
    size_t base = ((size_t)bh * NT + tpos) * ND;
    float2 x1 = *(const float2*)&src[base + 2 * fi];
    float2 x2 = *(const float2*)&src[base + 2 * fi + 64];
    float y1x, y1y, y2x, y2y;
    {
        float f = 2.0f * fi;
        float th = powf(10000.0f, -f * (1.0f / 64.0f));
        float s, c; sincosf((float)tpos * th, &s, &c);
        y1x = x1.x * c - x2.x * s;  y2x = x1.x * s + x2.x * c;
    }
    {
        float f = 2.0f * fi + 1.0f;
        float th = powf(10000.0f, -f * (1.0f / 64.0f));
        float s, c; sincosf((float)tpos * th, &s, &c);
        y1y = x1.y * c - x2.y * s;  y2y = x1.y * s + x2.y * c;
    }
    *(uint32_t*)&dst[base + 2 * fi]      = packh(y1x, y1y);
    *(uint32_t*)&dst[base + 2 * fi + 64] = packh(y2x, y2y);
}

// ---------------------------------------------------------------------------
// v fp32 [bh][t][d] -> transposed fp16 [bh][d][t]
// ---------------------------------------------------------------------------
__global__ void vconv_kernel()
{
    __shared__ float tile[32][33];
    const int bh = blockIdx.z;
    const int t0 = blockIdx.x * 32, d0 = blockIdx.y * 32;
    const int tx = threadIdx.x, ty = threadIdx.y;
    const float* src = (const float*)g_v + (size_t)bh * NT * ND;
    #pragma unroll
    for (int i = 0; i < 32; i += 8)
        tile[ty + i][tx] = src[(size_t)(t0 + ty + i) * ND + d0 + tx];
    __syncthreads();
    __half* dh = (__half*)g_vT + (size_t)bh * ND * NT;
    #pragma unroll
    for (int i = 0; i < 32; i += 8) {
        size_t o = (size_t)(d0 + ty + i) * NT + t0 + tx;
        dh[o] = __float2half_rn(tile[tx][ty + i]);
    }
}

// ---------------------------------------------------------------------------
// Flash attention, plain fp16 mma.sync (unchanged from R11).
// smem: 3 x 32KB K/V stages + Q 32KB = 128KB.
// ---------------------------------------------------------------------------
#define ASTG 32768
#define ATTN_SMEM (3*ASTG + 32768)   // 131072

__device__ __forceinline__ void attn_load_kv(uint32_t stg, int t, int bh, int kb)
{
    const size_t koff = ((size_t)bh * NT + kb * 64) * ND;
    #pragma unroll
    for (int i = 0; i < 4; ++i) {
        int idx = t + i * 256;
        int r = idx >> 4, c = idx & 15;
        uint32_t dst = stg + r * 256 + ((c ^ (r & 7)) << 4);
        cp16(dst, (const __half*)g_kh + koff + (size_t)r * ND + c * 8);
    }
    const size_t voff = (size_t)bh * ND * NT + kb * 64;
    #pragma unroll
    for (int i = 0; i < 4; ++i) {
        int idx = t + i * 256;
        int r = idx >> 3, c = idx & 7;
        uint32_t dst = stg + 16384 + r * 128 + ((c ^ (r & 7)) << 4);
        cp16(dst, (const __half*)g_vT + voff + (size_t)r * NT + c * 8);
    }
    asm volatile("cp.async.commit_group;" ::: "memory");
}

__global__ __launch_bounds__(256, 1)
void attn_mma_kernel()
{
    extern __shared__ __align__(1024) char abuf[];
    uint32_t sb = smem_u32(abuf);
    const int t = threadIdx.x, lane = t & 31, w = t >> 5;
    const int lam = lane & 3, ldiv = lane >> 2;
    const int g = lane >> 3, r8 = lane & 7;
    const int qb = 15 - (int)blockIdx.x;   // heavy q-blocks first
    const int bh = blockIdx.y;
    const float C1 = 0.08838834764831845f * 1.4426950408889634f; // scale*log2e

    // Q tile (128 x 128) plain fp16: 128 rows x 16 chunks = 2048 chunks
    const uint32_t qreg = sb + 3 * ASTG;
    const size_t qoff = ((size_t)bh * NT + qb * 128) * ND;
    #pragma unroll
    for (int i = 0; i < 8; ++i) {
        int idx = t + i * 256;
        int r = idx >> 4, c = idx & 15;
        uint32_t dst = qreg + r * 256 + ((c ^ (r & 7)) << 4);
        cp16(dst, (const __half*)g_qh + qoff + (size_t)r * ND + c * 8);
    }
    asm volatile("cp.async.commit_group;" ::: "memory");   // group: Q
    const int nkt = 2 * qb + 2;
    attn_load_kv(sb,        t, bh, 0);
    attn_load_kv(sb + ASTG, t, bh, 1);

    // Hoist Q fragments to registers
    asm volatile("cp.async.wait_group 2;" ::: "memory");
    __syncthreads();
    uint32_t qh[8][4];
    {
        const uint32_t aQ = qreg + (uint32_t)(w * 16 + (g & 1) * 8 + r8) * 256;
        #pragma unroll
        for (int s = 0; s < 8; ++s) {
            uint32_t cA = ((uint32_t)(2 * s + (g >> 1)) ^ (uint32_t)r8) << 4;
            ldm4(qh[s], aQ + cA);
        }
    }

    float oacc[16][4];
    #pragma unroll
    for (int i = 0; i < 16; ++i)
        #pragma unroll
        for (int j = 0; j < 4; ++j) oacc[i][j] = 0.f;
    float m0 = -INFINITY, m1 = -INFINITY, l0 = 0.f, l1 = 0.f;

    const int rowbase = qb * 128 + w * 16;

    int bc = 0, bl2 = 2;
    #pragma unroll 1
    for (int kb = 0; kb < nkt; ++kb) {
        if (kb == nkt - 1) asm volatile("cp.async.wait_group 0;" ::: "memory");
        else               asm volatile("cp.async.wait_group 1;" ::: "memory");
        __syncthreads();
        if (kb + 2 < nkt) attn_load_kv(sb + bl2 * ASTG, t, bh, kb + 2);
        uint32_t stg = sb + bc * ASTG;
        bc  = (bc  == 2) ? 0 : bc  + 1;
        bl2 = (bl2 == 2) ? 0 : bl2 + 1;

        if (kb * 64 <= rowbase + 15) {
            // ---- S = Q K^T (plain fp16) ----
            float sacc[8][4];
            #pragma unroll
            for (int i = 0; i < 8; ++i)
                #pragma unroll
                for (int j = 0; j < 4; ++j) sacc[i][j] = 0.f;

            const uint32_t aK = stg + (uint32_t)((g >> 1) * 8 + r8) * 256;
            #pragma unroll
            for (int s = 0; s < 8; ++s) {
                uint32_t cB = ((uint32_t)(2 * s + (g & 1)) ^ (uint32_t)r8) << 4;
                #pragma unroll
                for (int ng = 0; ng < 4; ++ng) {
                    uint32_t k4[4];
                    ldm4(k4, aK + (uint32_t)ng * (16 * 256) + cB);
                    mma_f16(sacc[ng*2],   qh[s], &k4[0]);
                    mma_f16(sacc[ng*2+1], qh[s], &k4[2]);
                }
            }

            // ---- scale (+ causal mask on diagonal tiles), log2 domain ----
            if (kb >= 2 * qb) {
                #pragma unroll
                for (int nt = 0; nt < 8; ++nt)
                    #pragma unroll
                    for (int j = 0; j < 4; ++j) {
                        int col = kb * 64 + nt * 8 + lam * 2 + (j & 1);
                        int row = rowbase + ldiv + ((j >> 1) << 3);
                        sacc[nt][j] = (col <= row) ? sacc[nt][j] * C1 : -1e30f;
                    }
            } else {
                #pragma unroll
                for (int nt = 0; nt < 8; ++nt)
                    #pragma unroll
                    for (int j = 0; j < 4; ++j) sacc[nt][j] *= C1;
            }

            // ---- online softmax (rows r and r+8) ----
            float mr0 = -1e30f, mr1 = -1e30f;
            #pragma unroll
            for (int nt = 0; nt < 8; ++nt) {
                mr0 = fmaxf(mr0, fmaxf(sacc[nt][0], sacc[nt][1]));
                mr1 = fmaxf(mr1, fmaxf(sacc[nt][2], sacc[nt][3]));
            }
            mr0 = fmaxf(mr0, __shfl_xor_sync(0xffffffffu, mr0, 1));
            mr0 = fmaxf(mr0, __shfl_xor_sync(0xffffffffu, mr0, 2));
            mr1 = fmaxf(mr1, __shfl_xor_sync(0xffffffffu, mr1, 1));
            mr1 = fmaxf(mr1, __shfl_xor_sync(0xffffffffu, mr1, 2));
            float mn0 = fmaxf(m0, mr0), mn1 = fmaxf(m1, mr1);
            float al0 = ex2(m0 - mn0), al1 = ex2(m1 - mn1);
            m0 = mn0; m1 = mn1;
            float ls0 = 0.f, ls1 = 0.f;
            #pragma unroll
            for (int nt = 0; nt < 8; ++nt) {
                float p0 = ex2(sacc[nt][0] - mn0);
                float p1 = ex2(sacc[nt][1] - mn0);
                float p2 = ex2(sacc[nt][2] - mn1);
                float p3 = ex2(sacc[nt][3] - mn1);
                sacc[nt][0] = p0; sacc[nt][1] = p1;
                sacc[nt][2] = p2; sacc[nt][3] = p3;
                ls0 += p0 + p1;  ls1 += p2 + p3;
            }
            ls0 += __shfl_xor_sync(0xffffffffu, ls0, 1);
            ls0 += __shfl_xor_sync(0xffffffffu, ls0, 2);
            ls1 += __shfl_xor_sync(0xffffffffu, ls1, 1);
            ls1 += __shfl_xor_sync(0xffffffffu, ls1, 2);
            l0 = l0 * al0 + ls0;  l1 = l1 * al1 + ls1;
            #pragma unroll
            for (int i = 0; i < 16; ++i) {
                oacc[i][0] *= al0;  oacc[i][1] *= al0;
                oacc[i][2] *= al1;  oacc[i][3] *= al1;
            }

            // ---- O += P V (plain fp16 P) ----
            const uint32_t aV = stg + 16384 + (uint32_t)((g >> 1) * 8 + r8) * 128;
            #pragma unroll
            for (int s2 = 0; s2 < 4; ++s2) {
                uint32_t ph[4];
                ph[0] = packh(sacc[2*s2][0],   sacc[2*s2][1]);
                ph[1] = packh(sacc[2*s2][2],   sacc[2*s2][3]);
                ph[2] = packh(sacc[2*s2+1][0], sacc[2*s2+1][1]);
                ph[3] = packh(sacc[2*s2+1][2], sacc[2*s2+1][3]);
                uint32_t cV = ((uint32_t)(2 * s2 + (g & 1)) ^ (uint32_t)r8) << 4;
                #pragma unroll
                for (int ng = 0; ng < 8; ++ng) {
                    uint32_t v4[4];
                    ldm4(v4, aV + (uint32_t)ng * (16 * 128) + cV);
                    mma_f16(oacc[ng*2],   ph, &v4[0]);
                    mma_f16(oacc[ng*2+1], ph, &v4[2]);
                }
            }
        }
    }

    // ---- finalize: /l, write fp16 att [b,t,h*128+d] ----
    float inv0 = 1.f / l0, inv1 = 1.f / l1;
    const int b = bh >> 4, h = bh & 15;
    const int row0 = qb * 128 + w * 16 + ldiv;
    const size_t obase = ((size_t)b * NT + row0) * NC + h * ND;
    #pragma unroll
    for (int nt = 0; nt < 16; ++nt) {
        const int d = nt * 8 + lam * 2;
        *(uint32_t*)&g_attf[obase + d]          = packh(oacc[nt][0] * inv0, oacc[nt][1] * inv0);
        *(uint32_t*)&g_attf[obase + 8 * NC + d] = packh(oacc[nt][2] * inv1, oacc[nt][3] * inv1);
    }
}

// ---------------------------------------------------------------------------
// Launch
// ---------------------------------------------------------------------------
extern "C" void kernel_launch(void* const* d_in, const int* in_sizes, int n_in,
                              void* d_out, int out_size)
{
    const float* x    = (const float*)d_in[0];
    const float* Wqkv = (const float*)d_in[1];
    const float* bqkv = (const float*)d_in[2];
    const float* Wo   = (const float*)d_in[3];
    const float* bo   = (const float*)d_in[4];
    float* out = (float*)d_out;

    cudaFuncSetAttribute(gemm_fp16<0>,
                         cudaFuncAttributeMaxDynamicSharedMemorySize, GEMM_SMEM);
    cudaFuncSetAttribute(gemm_fp16<1>,
                         cudaFuncAttributeMaxDynamicSharedMemorySize, GEMM_SMEM);
    cudaFuncSetAttribute(attn_mma_kernel,
                         cudaFuncAttributeMaxDynamicSharedMemorySize, ATTN_SMEM);

    __half *xh, *Wh, *Woh, *attf;
    cudaGetSymbolAddress((void**)&xh,   g_xh);
    cudaGetSymbolAddress((void**)&Wh,   g_Wh);
    cudaGetSymbolAddress((void**)&Woh,  g_Woh);
    cudaGetSymbolAddress((void**)&attf, g_attf);

    // 1) conversions: x -> fp16 ; Wqkv^T, Wo^T -> fp16
    conv_f16_kernel<<<16384, 256>>>(x, xh, 4194304);
    transpose_conv_kernel<<<dim3(192, 64), dim3(32, 8)>>>(Wqkv, Wh, 2048, 6144);
    transpose_conv_kernel<<<dim3(64, 64),  dim3(32, 8)>>>(Wo, Woh, 2048, 2048);

    // 2) QKV = x @ Wqkv + bqkv (fp16 mma, BN=256) -> g_q/g_k/g_v fp32 head-major
    gemm_fp16<0><<<dim3(24, 64), 256, GEMM_SMEM>>>(xh, Wh, bqkv, nullptr);

    // 3) RoPE + fp16 conversion (q and k plain)
    rope_conv_kernel<<<32768, 256>>>();

    // 4) v transpose -> fp16 [bh][d][t]
    vconv_kernel<<<dim3(64, 4, 64), dim3(32, 8)>>>();

    // 5) flash attention (plain fp16 mma.sync) -> g_attf
    attn_mma_kernel<<<dim3(16, 64), 256, ATTN_SMEM>>>();

    // 6) out = att @ Wo + bo (fp16 mma, BN=256)
    gemm_fp16<1><<<dim3(8, 64), 256, GEMM_SMEM>>>(attf, Woh, bo, out);
}

// round 15
// speedup vs baseline: 1.0847x; 1.0847x over previous
#include <cuda_runtime.h>
#include <cuda_fp16.h>
#include <math.h>
#include <stdint.h>

// Problem dims (fixed by reference)
#define NB 4
#define NT 2048
#define NC 2048
#define NH 16
#define ND 128
#define NBH (NB*NH)          // 64
#define M1 (NB*NT)           // 8192
#define KDIM 2048

// ---------------------------------------------------------------------------
// Device scratch (allocation-free rule: __device__ globals)
// ---------------------------------------------------------------------------
__device__ __align__(256) float g_q[16777216];   // [B*H][T][D] fp32 (pre-rope)
__device__ __align__(256) float g_k[16777216];
__device__ __align__(256) float g_v[16777216];

__device__ __align__(256) __half g_xh[16777216];    // x fp16     [8192][2048]
__device__ __align__(256) __half g_Wh[12582912];    // Wqkv^T     [6144][2048]
__device__ __align__(256) __half g_Woh[4194304];    // Wo^T       [2048][2048]
__device__ __align__(256) __half g_attf[16777216];  // att fp16   [8192][2048]

__device__ __align__(256) __half g_qh[16777216];    // rope'd q fp16 [bh][t][d]
__device__ __align__(256) __half g_kh[16777216];    // rope'd k fp16 [bh][t][d]
__device__ __align__(256) __half g_vT[16777216];    // v^T fp16      [bh][d][t]

// ---------------------------------------------------------------------------
// PTX helpers (Ampere-class, valid under compute_103)
// ---------------------------------------------------------------------------
__device__ __forceinline__ uint32_t smem_u32(const void* p) {
    uint32_t a;
    asm("{ .reg .u64 t; cvta.to.shared.u64 t, %1; cvt.u32.u64 %0, t; }"
        : "=r"(a) : "l"(p));
    return a;
}
__device__ __forceinline__ void cp16(uint32_t s, const void* g) {
    asm volatile("cp.async.cg.shared.global [%0], [%1], 16;" :: "r"(s), "l"(g));
}
__device__ __forceinline__ void ldm4(uint32_t* r, uint32_t addr) {
    asm volatile("ldmatrix.sync.aligned.m8n8.x4.shared.b16 {%0,%1,%2,%3}, [%4];"
                 : "=r"(r[0]), "=r"(r[1]), "=r"(r[2]), "=r"(r[3]) : "r"(addr));
}
__device__ __forceinline__ void mma_f16(float* c, const uint32_t* a, const uint32_t* b) {
    asm volatile(
        "mma.sync.aligned.m16n8k16.row.col.f32.f16.f16.f32 "
        "{%0,%1,%2,%3}, {%4,%5,%6,%7}, {%8,%9}, {%0,%1,%2,%3};"
        : "+f"(c[0]), "+f"(c[1]), "+f"(c[2]), "+f"(c[3])
        : "r"(a[0]), "r"(a[1]), "r"(a[2]), "r"(a[3]), "r"(b[0]), "r"(b[1]));
}
__device__ __forceinline__ float ex2(float x) {
    float y; asm("ex2.approx.f32 %0, %1;" : "=f"(y) : "f"(x)); return y;
}
__device__ __forceinline__ uint32_t packh(float x, float y) {
    __half2 h = __floats2half2_rn(x, y);
    return *(uint32_t*)&h;
}

// ---------------------------------------------------------------------------
// Plain fp16 mma.sync GEMM (R12 config — known best): C[M,N] = A[M,K] @ B^T
// BM=128 BN=128 BK=64, 8 warps (2x4). 3-stage, 1 sync/stage, 96KB, 2 CTAs/SM.
// ---------------------------------------------------------------------------
#define BK 64
#define NKCH (KDIM/BK)       // 32
#define STG_SZ 32768
#define GEMM_SMEM (3*STG_SZ) // 98304

__device__ __forceinline__ void load_stage32(
    uint32_t stg, int t, int koff,
    const __half* pA, const __half* pB)
{
    #pragma unroll
    for (int i = 0; i < 4; ++i) {
        int idx = t + i * 256;
        int r = idx >> 3, ci = idx & 7;
        uint32_t so = stg + r * 128 + ((ci ^ (r & 7)) << 4);
        size_t go = (size_t)r * KDIM + koff + ci * 8;
        cp16(so,          pA + go);
        cp16(so + 16384,  pB + go);
    }
    asm volatile("cp.async.commit_group;" ::: "memory");
}

__device__ __forceinline__ void compute_stage(
    uint32_t stg, int wm, int wn, int lane, float acc[4][4][4])
{
    const int r = lane & 7, g = lane >> 3;
    const uint32_t rx = (uint32_t)r << 4;
    const uint32_t baseA = stg + (uint32_t)(wm * 64 + (g & 1) * 8 + r) * 128;
    const uint32_t hA4   = (uint32_t)(g >> 1) << 4;
    const uint32_t baseB = stg + 16384 + (uint32_t)(wn * 32 + (g >> 1) * 8 + r) * 128;
    const uint32_t hB4   = (uint32_t)(g & 1) << 4;

    #pragma unroll
    for (int s = 0; s < 4; ++s) {
        const uint32_t offA = (((uint32_t)s << 5) | hA4) ^ rx;
        const uint32_t offB = (((uint32_t)s << 5) | hB4) ^ rx;
        uint32_t ah[4][4], bh[2][4];
        #pragma unroll
        for (int i = 0; i < 4; ++i)
            ldm4(ah[i], baseA + i * 2048 + offA);
        #pragma unroll
        for (int j = 0; j < 2; ++j)
            ldm4(bh[j], baseB + j * 2048 + offB);
        #pragma unroll
        for (int i = 0; i < 4; ++i)
            #pragma unroll
            for (int q = 0; q < 4; ++q)
                mma_f16(acc[i][q], ah[i], &bh[q >> 1][(q & 1) * 2]);
    }
}

template<int EPI>
__global__ __launch_bounds__(256, 2)
void gemm_fp16(const __half* __restrict__ A, const __half* __restrict__ B,
               const float* __restrict__ bias, float* __restrict__ C)
{
    extern __shared__ __align__(1024) char smbuf[];
    uint32_t sb = smem_u32(smbuf);
    const int t    = threadIdx.x;
    const int lane = t & 31, wid = t >> 5;
    const int wm   = wid >> 2, wn = wid & 3;
    const int m0   = blockIdx.y * 128;
    const int n0   = blockIdx.x * 128;

    float acc[4][4][4];
    #pragma unroll
    for (int i = 0; i < 4; ++i)
        #pragma unroll
        for (int q = 0; q < 4; ++q)
            #pragma unroll
            for (int k = 0; k < 4; ++k) acc[i][q][k] = 0.f;

    const __half* pA = A + (size_t)m0 * KDIM;
    const __half* pB = B + (size_t)n0 * KDIM;

    load_stage32(sb,          t, 0,  pA, pB);
    load_stage32(sb + STG_SZ, t, BK, pA, pB);

    int bc = 0, bl2 = 2;
    #pragma unroll 1
    for (int kt = 0; kt < NKCH; ++kt) {
        if (kt == NKCH - 1) asm volatile("cp.async.wait_group 0;" ::: "memory");
        else                asm volatile("cp.async.wait_group 1;" ::: "memory");
        __syncthreads();
        if (kt + 2 < NKCH)
            load_stage32(sb + bl2 * STG_SZ, t, (kt + 2) * BK, pA, pB);
        compute_stage(sb + bc * STG_SZ, wm, wn, lane, acc);
        bc  = (bc  == 2) ? 0 : bc  + 1;
        bl2 = (bl2 == 2) ? 0 : bl2 + 1;
    }

    const int mr  = (lane >> 2);
    const int nc0 = (lane & 3) * 2;
    if (EPI == 0) {
        const int which = n0 >> 11;
        const int h     = (n0 >> 7) & 15;
        float* dst = (which == 0) ? (float*)g_q
                   : (which == 1) ? (float*)g_k : (float*)g_v;
        const int b = m0 >> 11;
        #pragma unroll
        for (int i = 0; i < 4; ++i) {
            const int m  = m0 + wm * 64 + i * 16 + mr;
            const int tq = m & 2047;
            #pragma unroll
            for (int q = 0; q < 4; ++q) {
                const int dl = wn * 32 + q * 8 + nc0;
                float2 bs = *(const float2*)&bias[n0 + dl];
                size_t off = ((size_t)(b * 16 + h) * NT + tq) * ND + dl;
                float2 v0, v1;
                v0.x = acc[i][q][0] + bs.x;  v0.y = acc[i][q][1] + bs.y;
                v1.x = acc[i][q][2] + bs.x;  v1.y = acc[i][q][3] + bs.y;
                *(float2*)&dst[off]            = v0;
                *(float2*)&dst[off + 8 * ND]   = v1;
            }
        }
    } else {
        #pragma unroll
        for (int i = 0; i < 4; ++i) {
            const int m = m0 + wm * 64 + i * 16 + mr;
            #pragma unroll
            for (int q = 0; q < 4; ++q) {
                const int n = n0 + wn * 32 + q * 8 + nc0;
                float2 bs = *(const float2*)&bias[n];
                float2 v0, v1;
                v0.x = acc[i][q][0] + bs.x;  v0.y = acc[i][q][1] + bs.y;
                v1.x = acc[i][q][2] + bs.x;  v1.y = acc[i][q][3] + bs.y;
                *(float2*)&C[(size_t)m * NC + n]       = v0;
                *(float2*)&C[(size_t)(m + 8) * NC + n] = v1;
            }
        }
    }
}

// ---------------------------------------------------------------------------
// fp32 -> fp16 convert (x input)
// ---------------------------------------------------------------------------
__global__ void conv_f16_kernel(const float* __restrict__ in,
                                __half* __restrict__ out, int n4)
{
    int i = blockIdx.x * blockDim.x + threadIdx.x;
    if (i >= n4) return;
    float4 v = ((const float4*)in)[i];
    uint32_t* op = (uint32_t*)out;
    op[2 * i]     = packh(v.x, v.y);
    op[2 * i + 1] = packh(v.z, v.w);
}

// ---------------------------------------------------------------------------
// fp32 [K][N] -> transposed fp16 [N][K]  (weights)
// ---------------------------------------------------------------------------
__global__ void transpose_conv_kernel(const float* __restrict__ in,
                                      __half* __restrict__ out,
                                      int K, int N)
{
    __shared__ float tile[32][33];
    const int n0 = blockIdx.x * 32, k0 = blockIdx.y * 32;
    const int tx = threadIdx.x, ty = threadIdx.y;
    #pragma unroll
    for (int i = 0; i < 32; i += 8)
        tile[ty + i][tx] = in[(size_t)(k0 + ty + i) * N + n0 + tx];
    __syncthreads();
    #pragma unroll
    for (int i = 0; i < 32; i += 8) {
        size_t o = (size_t)(n0 + ty + i) * K + k0 + tx;
        out[o] = __float2half_rn(tile[tx][ty + i]);
    }
}

// ---------------------------------------------------------------------------
// RoPE fused with fp16 conversion: q and k -> plain fp16 (same path)
// ---------------------------------------------------------------------------
__global__ void rope_conv_kernel()
{
    const int PER = NBH * NT * 32;  // 4194304
    int idx = blockIdx.x * blockDim.x + threadIdx.x;
    const bool isK = idx >= PER;
    int r = isK ? idx - PER : idx;
    const float* src = isK ? (const float*)g_k : (const float*)g_q;
    __half* dst = isK ? (__half*)g_kh : (__half*)g_qh;
    int fi   = r & 31;
    int tpos = (r >> 5) & (NT - 1);
    int bh   = r >> 16;
    size_t base = ((size_t)bh * NT + tpos) * ND;
    float2 x1 = *(const float2*)&src[base + 2 * fi];
    float2 x2 = *(const float2*)&src[base + 2 * fi + 64];
    float y1x, y1y, y2x, y2y;
    {
        float f = 2.0f * fi;
        float th = powf(10000.0f, -f * (1.0f / 64.0f));
        float s, c; sincosf((float)tpos * th, &s, &c);
        y1x = x1.x * c - x2.x * s;  y2x = x1.x * s + x2.x * c;
    }
    {
        float f = 2.0f * fi + 1.0f;
        float th = powf(10000.0f, -f * (1.0f / 64.0f));
        float s, c; sincosf((float)tpos * th, &s, &c);
        y1y = x1.y * c - x2.y * s;  y2y = x1.y * s + x2.y * c;
    }
    *(uint32_t*)&dst[base + 2 * fi]      = packh(y1x, y1y);
    *(uint32_t*)&dst[base + 2 * fi + 64] = packh(y2x, y2y);
}

// ---------------------------------------------------------------------------
// v fp32 [bh][t][d] -> transposed fp16 [bh][d][t]
// ---------------------------------------------------------------------------
__global__ void vconv_kernel()
{
    __shared__ float tile[32][33];
    const int bh = blockIdx.z;
    const int t0 = blockIdx.x * 32, d0 = blockIdx.y * 32;
    const int tx = threadIdx.x, ty = threadIdx.y;
    const float* src = (const float*)g_v + (size_t)bh * NT * ND;
    #pragma unroll
    for (int i = 0; i < 32; i += 8)
        tile[ty + i][tx] = src[(size_t)(t0 + ty + i) * ND + d0 + tx];
    __syncthreads();
    __half* dh = (__half*)g_vT + (size_t)bh * ND * NT;
    #pragma unroll
    for (int i = 0; i < 32; i += 8) {
        size_t o = (size_t)(d0 + ty + i) * NT + t0 + tx;
        dh[o] = __float2half_rn(tile[tx][ty + i]);
    }
}

// ---------------------------------------------------------------------------
// Flash attention, plain fp16 mma.sync. BQ=128, BK=128 (one softmax per 128
// K-columns). 8 warps x 16 q-rows. 2-stage K/V pipeline (64KB stages) + Q 32KB.
// ---------------------------------------------------------------------------
#define ASTG 65536
#define ATTN_SMEM (2*ASTG + 32768)   // 163840

__device__ __forceinline__ void attn_load_kv(uint32_t stg, int t, int bh, int kb)
{
    const size_t koff = ((size_t)bh * NT + kb * 128) * ND;
    #pragma unroll
    for (int i = 0; i < 8; ++i) {          // K: 128 rows x 16 chunks
        int idx = t + i * 256;
        int r = idx >> 4, c = idx & 15;
        uint32_t dst = stg + r * 256 + ((c ^ (r & 7)) << 4);
        cp16(dst, (const __half*)g_kh + koff + (size_t)r * ND + c * 8);
    }
    const size_t voff = (size_t)bh * ND * NT + kb * 128;
    #pragma unroll
    for (int i = 0; i < 8; ++i) {          // V: 128 d-rows x 16 chunks (t)
        int idx = t + i * 256;
        int r = idx >> 4, c = idx & 15;
        uint32_t dst = stg + 32768 + r * 256 + ((c ^ (r & 7)) << 4);
        cp16(dst, (const __half*)g_vT + voff + (size_t)r * NT + c * 8);
    }
    asm volatile("cp.async.commit_group;" ::: "memory");
}

__global__ __launch_bounds__(256, 1)
void attn_mma_kernel()
{
    extern __shared__ __align__(1024) char abuf[];
    uint32_t sb = smem_u32(abuf);
    const int t = threadIdx.x, lane = t & 31, w = t >> 5;
    const int lam = lane & 3, ldiv = lane >> 2;
    const int g = lane >> 3, r8 = lane & 7;
    const int qb = 15 - (int)blockIdx.x;   // heavy q-blocks first
    const int bh = blockIdx.y;
    const float C1 = 0.08838834764831845f * 1.4426950408889634f; // scale*log2e

    // Q tile (128 x 128) plain fp16
    const uint32_t qreg = sb + 2 * ASTG;
    const size_t qoff = ((size_t)bh * NT + qb * 128) * ND;
    #pragma unroll
    for (int i = 0; i < 8; ++i) {
        int idx = t + i * 256;
        int r = idx >> 4, c = idx & 15;
        uint32_t dst = qreg + r * 256 + ((c ^ (r & 7)) << 4);
        cp16(dst, (const __half*)g_qh + qoff + (size_t)r * ND + c * 8);
    }
    asm volatile("cp.async.commit_group;" ::: "memory");   // group: Q
    const int nkt = qb + 1;
    attn_load_kv(sb, t, bh, 0);
    if (nkt > 1) attn_load_kv(sb + ASTG, t, bh, 1);

    // Hoist Q fragments to registers.
    // FIX (R14 NaN): wait until Q's group is complete. Groups retire in-order;
    // Q is the OLDEST group, so wait_group <#KV groups committed> drains Q.
    if (nkt > 1) asm volatile("cp.async.wait_group 2;" ::: "memory");
    else         asm volatile("cp.async.wait_group 1;" ::: "memory");
    __syncthreads();
    uint32_t qh[8][4];
    {
        const uint32_t aQ = qreg + (uint32_t)(w * 16 + (g & 1) * 8 + r8) * 256;
        #pragma unroll
        for (int s = 0; s < 8; ++s) {
            uint32_t cA = ((uint32_t)(2 * s + (g >> 1)) ^ (uint32_t)r8) << 4;
            ldm4(qh[s], aQ + cA);
        }
    }

    float oacc[16][4];
    #pragma unroll
    for (int i = 0; i < 16; ++i)
        #pragma unroll
        for (int j = 0; j < 4; ++j) oacc[i][j] = 0.f;
    float m0 = -INFINITY, m1 = -INFINITY, l0 = 0.f, l1 = 0.f;

    const int rowbase = qb * 128 + w * 16;

    #pragma unroll 1
    for (int kb = 0; kb < nkt; ++kb) {
        if (kb == nkt - 1) asm volatile("cp.async.wait_group 0;" ::: "memory");
        else               asm volatile("cp.async.wait_group 1;" ::: "memory");
        __syncthreads();
        uint32_t stg = sb + (kb & 1) * ASTG;

        // ---- S = Q K^T (plain fp16, 128x128 per block tile) ----
        float sacc[16][4];
        #pragma unroll
        for (int i = 0; i < 16; ++i)
            #pragma unroll
            for (int j = 0; j < 4; ++j) sacc[i][j] = 0.f;

        const uint32_t aK = stg + (uint32_t)((g >> 1) * 8 + r8) * 256;
        #pragma unroll
        for (int s = 0; s < 8; ++s) {
            uint32_t cB = ((uint32_t)(2 * s + (g & 1)) ^ (uint32_t)r8) << 4;
            #pragma unroll
            for (int ng = 0; ng < 8; ++ng) {
                uint32_t k4[4];
                ldm4(k4, aK + (uint32_t)ng * (16 * 256) + cB);
                mma_f16(sacc[ng*2],   qh[s], &k4[0]);
                mma_f16(sacc[ng*2+1], qh[s], &k4[2]);
            }
        }

        // ---- scale (+ causal mask on the diagonal tile), log2 domain ----
        if (kb == qb) {
            #pragma unroll
            for (int nt = 0; nt < 16; ++nt)
                #pragma unroll
                for (int j = 0; j < 4; ++j) {
                    int col = kb * 128 + nt * 8 + lam * 2 + (j & 1);
                    int row = rowbase + ldiv + ((j >> 1) << 3);
                    sacc[nt][j] = (col <= row) ? sacc[nt][j] * C1 : -1e30f;
                }
        } else {
            #pragma unroll
            for (int nt = 0; nt < 16; ++nt)
                #pragma unroll
                for (int j = 0; j < 4; ++j) sacc[nt][j] *= C1;
        }

        // ---- online softmax (rows r and r+8) ----
        float mr0 = -1e30f, mr1 = -1e30f;
        #pragma unroll
        for (int nt = 0; nt < 16; ++nt) {
            mr0 = fmaxf(mr0, fmaxf(sacc[nt][0], sacc[nt][1]));
            mr1 = fmaxf(mr1, fmaxf(sacc[nt][2], sacc[nt][3]));
        }
        mr0 = fmaxf(mr0, __shfl_xor_sync(0xffffffffu, mr0, 1));
        mr0 = fmaxf(mr0, __shfl_xor_sync(0xffffffffu, mr0, 2));
        mr1 = fmaxf(mr1, __shfl_xor_sync(0xffffffffu, mr1, 1));
        mr1 = fmaxf(mr1, __shfl_xor_sync(0xffffffffu, mr1, 2));
        float mn0 = fmaxf(m0, mr0), mn1 = fmaxf(m1, mr1);
        float al0 = ex2(m0 - mn0), al1 = ex2(m1 - mn1);
        m0 = mn0; m1 = mn1;
        float ls0 = 0.f, ls1 = 0.f;
        #pragma unroll
        for (int nt = 0; nt < 16; ++nt) {
            float p0 = ex2(sacc[nt][0] - mn0);
            float p1 = ex2(sacc[nt][1] - mn0);
            float p2 = ex2(sacc[nt][2] - mn1);
            float p3 = ex2(sacc[nt][3] - mn1);
            sacc[nt][0] = p0; sacc[nt][1] = p1;
            sacc[nt][2] = p2; sacc[nt][3] = p3;
            ls0 += p0 + p1;  ls1 += p2 + p3;
        }
        ls0 += __shfl_xor_sync(0xffffffffu, ls0, 1);
        ls0 += __shfl_xor_sync(0xffffffffu, ls0, 2);
        ls1 += __shfl_xor_sync(0xffffffffu, ls1, 1);
        ls1 += __shfl_xor_sync(0xffffffffu, ls1, 2);
        l0 = l0 * al0 + ls0;  l1 = l1 * al1 + ls1;
        #pragma unroll
        for (int i = 0; i < 16; ++i) {
            oacc[i][0] *= al0;  oacc[i][1] *= al0;
            oacc[i][2] *= al1;  oacc[i][3] *= al1;
        }

        // ---- O += P V (plain fp16 P, contraction over 128 t) ----
        const uint32_t aV = stg + 32768 + (uint32_t)((g >> 1) * 8 + r8) * 256;
        #pragma unroll
        for (int s2 = 0; s2 < 8; ++s2) {
            uint32_t ph[4];
            ph[0] = packh(sacc[2*s2][0],   sacc[2*s2][1]);
            ph[1] = packh(sacc[2*s2][2],   sacc[2*s2][3]);
            ph[2] = packh(sacc[2*s2+1][0], sacc[2*s2+1][1]);
            ph[3] = packh(sacc[2*s2+1][2], sacc[2*s2+1][3]);
            uint32_t cV = ((uint32_t)(2 * s2 + (g & 1)) ^ (uint32_t)r8) << 4;
            #pragma unroll
            for (int ng = 0; ng < 8; ++ng) {
                uint32_t v4[4];
                ldm4(v4, aV + (uint32_t)ng * (16 * 256) + cV);
                mma_f16(oacc[ng*2],   ph, &v4[0]);
                mma_f16(oacc[ng*2+1], ph, &v4[2]);
            }
        }

        __syncthreads();   // compute done before next load overwrites buffer
        if (kb + 2 < nkt) attn_load_kv(sb + (kb & 1) * ASTG, t, bh, kb + 2);
    }

    // ---- finalize: /l, write fp16 att [b,t,h*128+d] ----
    float inv0 = 1.f / l0, inv1 = 1.f / l1;
    const int b = bh >> 4, h = bh & 15;
    const int row0 = qb * 128 + w * 16 + ldiv;
    const size_t obase = ((size_t)b * NT + row0) * NC + h * ND;
    #pragma unroll
    for (int nt = 0; nt < 16; ++nt) {
        const int d = nt * 8 + lam * 2;
        *(uint32_t*)&g_attf[obase + d]          = packh(oacc[nt][0] * inv0, oacc[nt][1] * inv0);
        *(uint32_t*)&g_attf[obase + 8 * NC + d] = packh(oacc[nt][2] * inv1, oacc[nt][3] * inv1);
    }
}

// ---------------------------------------------------------------------------
// Launch
// ---------------------------------------------------------------------------
extern "C" void kernel_launch(void* const* d_in, const int* in_sizes, int n_in,
                              void* d_out, int out_size)
{
    const float* x    = (const float*)d_in[0];
    const float* Wqkv = (const float*)d_in[1];
    const float* bqkv = (const float*)d_in[2];
    const float* Wo   = (const float*)d_in[3];
    const float* bo   = (const float*)d_in[4];
    float* out = (float*)d_out;

    cudaFuncSetAttribute(gemm_fp16<0>,
                         cudaFuncAttributeMaxDynamicSharedMemorySize, GEMM_SMEM);
    cudaFuncSetAttribute(gemm_fp16<1>,
                         cudaFuncAttributeMaxDynamicSharedMemorySize, GEMM_SMEM);
    cudaFuncSetAttribute(attn_mma_kernel,
                         cudaFuncAttributeMaxDynamicSharedMemorySize, ATTN_SMEM);

    __half *xh, *Wh, *Woh, *attf;
    cudaGetSymbolAddress((void**)&xh,   g_xh);
    cudaGetSymbolAddress((void**)&Wh,   g_Wh);
    cudaGetSymbolAddress((void**)&Woh,  g_Woh);
    cudaGetSymbolAddress((void**)&attf, g_attf);

    // 1) conversions: x -> fp16 ; Wqkv^T, Wo^T -> fp16
    conv_f16_kernel<<<16384, 256>>>(x, xh, 4194304);
    transpose_conv_kernel<<<dim3(192, 64), dim3(32, 8)>>>(Wqkv, Wh, 2048, 6144);
    transpose_conv_kernel<<<dim3(64, 64),  dim3(32, 8)>>>(Wo, Woh, 2048, 2048);

    // 2) QKV = x @ Wqkv + bqkv (fp16 mma) -> g_q/g_k/g_v fp32 head-major
    gemm_fp16<0><<<dim3(48, 64), 256, GEMM_SMEM>>>(xh, Wh, bqkv, nullptr);

    // 3) RoPE + fp16 conversion (q and k plain)
    rope_conv_kernel<<<32768, 256>>>();

    // 4) v transpose -> fp16 [bh][d][t]
    vconv_kernel<<<dim3(64, 4, 64), dim3(32, 8)>>>();

    // 5) flash attention (plain fp16 mma.sync, BK=128) -> g_attf
    attn_mma_kernel<<<dim3(16, 64), 256, ATTN_SMEM>>>();

    // 6) out = att @ Wo + bo (fp16 mma)
    gemm_fp16<1><<<dim3(16, 64), 256, GEMM_SMEM>>>(attf, Woh, bo, out);
}

// round 16
// speedup vs baseline: 1.1412x; 1.0521x over previous
#include <cuda_runtime.h>
#include <cuda_fp16.h>
#include <math.h>
#include <stdint.h>

// Problem dims (fixed by reference)
#define NB 4
#define NT 2048
#define NC 2048
#define NH 16
#define ND 128
#define NBH (NB*NH)          // 64
#define M1 (NB*NT)           // 8192
#define KDIM 2048

// ---------------------------------------------------------------------------
// Device scratch (allocation-free rule: __device__ globals)
// ---------------------------------------------------------------------------
__device__ __align__(256) __half g_xh[16777216];    // x fp16     [8192][2048]
__device__ __align__(256) __half g_Wh[12582912];    // Wqkv^T     [6144][2048]
__device__ __align__(256) __half g_Woh[4194304];    // Wo^T       [2048][2048]
__device__ __align__(256) __half g_attf[16777216];  // att fp16   [8192][2048]

__device__ __align__(256) __half g_qh[16777216];    // rope'd q fp16 [bh][t][d]
__device__ __align__(256) __half g_kh[16777216];    // rope'd k fp16 [bh][t][d]
__device__ __align__(256) __half g_vT[16777216];    // v^T fp16      [bh][d][t]

// ---------------------------------------------------------------------------
// PTX helpers (Ampere-class, valid under compute_103)
// ---------------------------------------------------------------------------
__device__ __forceinline__ uint32_t smem_u32(const void* p) {
    uint32_t a;
    asm("{ .reg .u64 t; cvta.to.shared.u64 t, %1; cvt.u32.u64 %0, t; }"
        : "=r"(a) : "l"(p));
    return a;
}
__device__ __forceinline__ void cp16(uint32_t s, const void* g) {
    asm volatile("cp.async.cg.shared.global [%0], [%1], 16;" :: "r"(s), "l"(g));
}
__device__ __forceinline__ void ldm4(uint32_t* r, uint32_t addr) {
    asm volatile("ldmatrix.sync.aligned.m8n8.x4.shared.b16 {%0,%1,%2,%3}, [%4];"
                 : "=r"(r[0]), "=r"(r[1]), "=r"(r[2]), "=r"(r[3]) : "r"(addr));
}
__device__ __forceinline__ void mma_f16(float* c, const uint32_t* a, const uint32_t* b) {
    asm volatile(
        "mma.sync.aligned.m16n8k16.row.col.f32.f16.f16.f32 "
        "{%0,%1,%2,%3}, {%4,%5,%6,%7}, {%8,%9}, {%0,%1,%2,%3};"
        : "+f"(c[0]), "+f"(c[1]), "+f"(c[2]), "+f"(c[3])
        : "r"(a[0]), "r"(a[1]), "r"(a[2]), "r"(a[3]), "r"(b[0]), "r"(b[1]));
}
__device__ __forceinline__ float ex2(float x) {
    float y; asm("ex2.approx.f32 %0, %1;" : "=f"(y) : "f"(x)); return y;
}
__device__ __forceinline__ uint32_t packh(float x, float y) {
    __half2 h = __floats2half2_rn(x, y);
    return *(uint32_t*)&h;
}

// ---------------------------------------------------------------------------
// Plain fp16 mma.sync GEMM: C[M,N] = A[M,K] @ B^T
// BM=128 BN=128 BK=64, 8 warps (2x4). 3-stage, 1 sync/stage, 96KB, 2 CTAs/SM.
// EPI==0: QKV epilogue — RoPE (q,k) / transpose (v) fused, fp16 outputs.
// EPI==1: bias + row-major fp32 store.
// ---------------------------------------------------------------------------
#define BK 64
#define NKCH (KDIM/BK)       // 32
#define STG_SZ 32768
#define GEMM_SMEM (3*STG_SZ) // 98304  (>= 128*129*4 = 66048 for epilogue tile)

__device__ __forceinline__ void load_stage32(
    uint32_t stg, int t, int koff,
    const __half* pA, const __half* pB)
{
    #pragma unroll
    for (int i = 0; i < 4; ++i) {
        int idx = t + i * 256;
        int r = idx >> 3, ci = idx & 7;
        uint32_t so = stg + r * 128 + ((ci ^ (r & 7)) << 4);
        size_t go = (size_t)r * KDIM + koff + ci * 8;
        cp16(so,          pA + go);
        cp16(so + 16384,  pB + go);
    }
    asm volatile("cp.async.commit_group;" ::: "memory");
}

__device__ __forceinline__ void compute_stage(
    uint32_t stg, int wm, int wn, int lane, float acc[4][4][4])
{
    const int r = lane & 7, g = lane >> 3;
    const uint32_t rx = (uint32_t)r << 4;
    const uint32_t baseA = stg + (uint32_t)(wm * 64 + (g & 1) * 8 + r) * 128;
    const uint32_t hA4   = (uint32_t)(g >> 1) << 4;
    const uint32_t baseB = stg + 16384 + (uint32_t)(wn * 32 + (g >> 1) * 8 + r) * 128;
    const uint32_t hB4   = (uint32_t)(g & 1) << 4;

    #pragma unroll
    for (int s = 0; s < 4; ++s) {
        const uint32_t offA = (((uint32_t)s << 5) | hA4) ^ rx;
        const uint32_t offB = (((uint32_t)s << 5) | hB4) ^ rx;
        uint32_t ah[4][4], bh[2][4];
        #pragma unroll
        for (int i = 0; i < 4; ++i)
            ldm4(ah[i], baseA + i * 2048 + offA);
        #pragma unroll
        for (int j = 0; j < 2; ++j)
            ldm4(bh[j], baseB + j * 2048 + offB);
        #pragma unroll
        for (int i = 0; i < 4; ++i)
            #pragma unroll
            for (int q = 0; q < 4; ++q)
                mma_f16(acc[i][q], ah[i], &bh[q >> 1][(q & 1) * 2]);
    }
}

template<int EPI>
__global__ __launch_bounds__(256, 2)
void gemm_fp16(const __half* __restrict__ A, const __half* __restrict__ B,
               const float* __restrict__ bias, float* __restrict__ C)
{
    extern __shared__ __align__(1024) char smbuf[];
    uint32_t sb = smem_u32(smbuf);
    const int t    = threadIdx.x;
    const int lane = t & 31, wid = t >> 5;
    const int wm   = wid >> 2, wn = wid & 3;
    const int m0   = blockIdx.y * 128;
    const int n0   = blockIdx.x * 128;

    float acc[4][4][4];
    #pragma unroll
    for (int i = 0; i < 4; ++i)
        #pragma unroll
        for (int q = 0; q < 4; ++q)
            #pragma unroll
            for (int k = 0; k < 4; ++k) acc[i][q][k] = 0.f;

    const __half* pA = A + (size_t)m0 * KDIM;
    const __half* pB = B + (size_t)n0 * KDIM;

    load_stage32(sb,          t, 0,  pA, pB);
    load_stage32(sb + STG_SZ, t, BK, pA, pB);

    int bc = 0, bl2 = 2;
    #pragma unroll 1
    for (int kt = 0; kt < NKCH; ++kt) {
        if (kt == NKCH - 1) asm volatile("cp.async.wait_group 0;" ::: "memory");
        else                asm volatile("cp.async.wait_group 1;" ::: "memory");
        __syncthreads();
        if (kt + 2 < NKCH)
            load_stage32(sb + bl2 * STG_SZ, t, (kt + 2) * BK, pA, pB);
        compute_stage(sb + bc * STG_SZ, wm, wn, lane, acc);
        bc  = (bc  == 2) ? 0 : bc  + 1;
        bl2 = (bl2 == 2) ? 0 : bl2 + 1;
    }

    const int mr  = (lane >> 2);
    const int nc0 = (lane & 3) * 2;
    if (EPI == 0) {
        // ---- fused QKV epilogue: stage biased fp32 tile in smem ----
        float* smf = (float*)smbuf;
        __syncthreads();   // pipeline smem is dead; others' compute done
        #pragma unroll
        for (int i = 0; i < 4; ++i) {
            const int ml = wm * 64 + i * 16 + mr;
            #pragma unroll
            for (int q = 0; q < 4; ++q) {
                const int dl = wn * 32 + q * 8 + nc0;
                float2 bs = *(const float2*)&bias[n0 + dl];
                smf[ml * 129 + dl]           = acc[i][q][0] + bs.x;
                smf[ml * 129 + dl + 1]       = acc[i][q][1] + bs.y;
                smf[(ml + 8) * 129 + dl]     = acc[i][q][2] + bs.x;
                smf[(ml + 8) * 129 + dl + 1] = acc[i][q][3] + bs.y;
            }
        }
        __syncthreads();
        const int which = n0 >> 11;          // 0=q 1=k 2=v
        const int h     = (n0 >> 7) & 15;
        const int b     = m0 >> 11;
        const int tq0   = m0 & 2047;
        const int bh    = b * 16 + h;
        if (which == 2) {
            // transpose: v[t][d] -> g_vT[bh][d][t] (fp16)
            __half* dv = (__half*)g_vT + (size_t)bh * ND * NT + tq0;
            #pragma unroll
            for (int it = 0; it < 32; ++it) {     // 128 d x 64 m-pairs
                int idx = t + it * 256;
                int d = idx >> 6, m2 = (idx & 63) * 2;
                float f0 = smf[m2 * 129 + d];
                float f1 = smf[(m2 + 1) * 129 + d];
                *(uint32_t*)&dv[(size_t)d * NT + m2] = packh(f0, f1);
            }
        } else {
            // RoPE + fp16: rows = t positions, pairs (2fi,2fi+1)&(+64,+65)
            __half* dq = ((which == 0) ? (__half*)g_qh : (__half*)g_kh)
                       + ((size_t)bh * NT + tq0) * ND;
            #pragma unroll
            for (int it = 0; it < 16; ++it) {     // 128 rows x 32 f-pairs
                int idx = t + it * 256;
                int row = idx >> 5, fi = idx & 31;
                const float* rp = smf + row * 129;
                float x1a = rp[2 * fi],      x1b = rp[2 * fi + 1];
                float x2a = rp[2 * fi + 64], x2b = rp[2 * fi + 65];
                float tpos = (float)(tq0 + row);
                float fa = 2.0f * fi;
                float th0 = powf(10000.0f, -fa * (1.0f / 64.0f));
                float s0, c0; sincosf(tpos * th0, &s0, &c0);
                float th1 = powf(10000.0f, -(fa + 1.0f) * (1.0f / 64.0f));
                float s1, c1; sincosf(tpos * th1, &s1, &c1);
                float y1a = x1a * c0 - x2a * s0, y2a = x1a * s0 + x2a * c0;
                float y1b = x1b * c1 - x2b * s1, y2b = x1b * s1 + x2b * c1;
                *(uint32_t*)&dq[(size_t)row * ND + 2 * fi]      = packh(y1a, y1b);
                *(uint32_t*)&dq[(size_t)row * ND + 2 * fi + 64] = packh(y2a, y2b);
            }
        }
    } else {
        #pragma unroll
        for (int i = 0; i < 4; ++i) {
            const int m = m0 + wm * 64 + i * 16 + mr;
            #pragma unroll
            for (int q = 0; q < 4; ++q) {
                const int n = n0 + wn * 32 + q * 8 + nc0;
                float2 bs = *(const float2*)&bias[n];
                float2 v0, v1;
                v0.x = acc[i][q][0] + bs.x;  v0.y = acc[i][q][1] + bs.y;
                v1.x = acc[i][q][2] + bs.x;  v1.y = acc[i][q][3] + bs.y;
                *(float2*)&C[(size_t)m * NC + n]       = v0;
                *(float2*)&C[(size_t)(m + 8) * NC + n] = v1;
            }
        }
    }
}

// ---------------------------------------------------------------------------
// fp32 -> fp16 convert (x input)
// ---------------------------------------------------------------------------
__global__ void conv_f16_kernel(const float* __restrict__ in,
                                __half* __restrict__ out, int n4)
{
    int i = blockIdx.x * blockDim.x + threadIdx.x;
    if (i >= n4) return;
    float4 v = ((const float4*)in)[i];
    uint32_t* op = (uint32_t*)out;
    op[2 * i]     = packh(v.x, v.y);
    op[2 * i + 1] = packh(v.z, v.w);
}

// ---------------------------------------------------------------------------
// fp32 [K][N] -> transposed fp16 [N][K]  (weights)
// ---------------------------------------------------------------------------
__global__ void transpose_conv_kernel(const float* __restrict__ in,
                                      __half* __restrict__ out,
                                      int K, int N)
{
    __shared__ float tile[32][33];
    const int n0 = blockIdx.x * 32, k0 = blockIdx.y * 32;
    const int tx = threadIdx.x, ty = threadIdx.y;
    #pragma unroll
    for (int i = 0; i < 32; i += 8)
        tile[ty + i][tx] = in[(size_t)(k0 + ty + i) * N + n0 + tx];
    __syncthreads();
    #pragma unroll
    for (int i = 0; i < 32; i += 8) {
        size_t o = (size_t)(n0 + ty + i) * K + k0 + tx;
        out[o] = __float2half_rn(tile[tx][ty + i]);
    }
}

// ---------------------------------------------------------------------------
// Flash attention, plain fp16 mma.sync (R11 proven config).
// BQ=128, BK=64, 8 warps. 3 x 32KB K/V stages + Q 32KB = 128KB.
// ---------------------------------------------------------------------------
#define ASTG 32768
#define ATTN_SMEM (3*ASTG + 32768)   // 131072

__device__ __forceinline__ void attn_load_kv(uint32_t stg, int t, int bh, int kb)
{
    const size_t koff = ((size_t)bh * NT + kb * 64) * ND;
    #pragma unroll
    for (int i = 0; i < 4; ++i) {
        int idx = t + i * 256;
        int r = idx >> 4, c = idx & 15;
        uint32_t dst = stg + r * 256 + ((c ^ (r & 7)) << 4);
        cp16(dst, (const __half*)g_kh + koff + (size_t)r * ND + c * 8);
    }
    const size_t voff = (size_t)bh * ND * NT + kb * 64;
    #pragma unroll
    for (int i = 0; i < 4; ++i) {
        int idx = t + i * 256;
        int r = idx >> 3, c = idx & 7;
        uint32_t dst = stg + 16384 + r * 128 + ((c ^ (r & 7)) << 4);
        cp16(dst, (const __half*)g_vT + voff + (size_t)r * NT + c * 8);
    }
    asm volatile("cp.async.commit_group;" ::: "memory");
}

__global__ __launch_bounds__(256, 1)
void attn_mma_kernel()
{
    extern __shared__ __align__(1024) char abuf[];
    uint32_t sb = smem_u32(abuf);
    const int t = threadIdx.x, lane = t & 31, w = t >> 5;
    const int lam = lane & 3, ldiv = lane >> 2;
    const int g = lane >> 3, r8 = lane & 7;
    const int qb = 15 - (int)blockIdx.x;   // heavy q-blocks first
    const int bh = blockIdx.y;
    const float C1 = 0.08838834764831845f * 1.4426950408889634f; // scale*log2e

    // Q tile (128 x 128) plain fp16: 128 rows x 16 chunks = 2048 chunks
    const uint32_t qreg = sb + 3 * ASTG;
    const size_t qoff = ((size_t)bh * NT + qb * 128) * ND;
    #pragma unroll
    for (int i = 0; i < 8; ++i) {
        int idx = t + i * 256;
        int r = idx >> 4, c = idx & 15;
        uint32_t dst = qreg + r * 256 + ((c ^ (r & 7)) << 4);
        cp16(dst, (const __half*)g_qh + qoff + (size_t)r * ND + c * 8);
    }
    asm volatile("cp.async.commit_group;" ::: "memory");   // group: Q
    const int nkt = 2 * qb + 2;
    attn_load_kv(sb,        t, bh, 0);
    attn_load_kv(sb + ASTG, t, bh, 1);

    // Hoist Q fragments to registers (Q oldest group; 2 KV groups pending ok)
    asm volatile("cp.async.wait_group 2;" ::: "memory");
    __syncthreads();
    uint32_t qh[8][4];
    {
        const uint32_t aQ = qreg + (uint32_t)(w * 16 + (g & 1) * 8 + r8) * 256;
        #pragma unroll
        for (int s = 0; s < 8; ++s) {
            uint32_t cA = ((uint32_t)(2 * s + (g >> 1)) ^ (uint32_t)r8) << 4;
            ldm4(qh[s], aQ + cA);
        }
    }

    float oacc[16][4];
    #pragma unroll
    for (int i = 0; i < 16; ++i)
        #pragma unroll
        for (int j = 0; j < 4; ++j) oacc[i][j] = 0.f;
    float m0 = -INFINITY, m1 = -INFINITY, l0 = 0.f, l1 = 0.f;

    const int rowbase = qb * 128 + w * 16;

    int bc = 0, bl2 = 2;
    #pragma unroll 1
    for (int kb = 0; kb < nkt; ++kb) {
        if (kb == nkt - 1) asm volatile("cp.async.wait_group 0;" ::: "memory");
        else               asm volatile("cp.async.wait_group 1;" ::: "memory");
        __syncthreads();
        if (kb + 2 < nkt) attn_load_kv(sb + bl2 * ASTG, t, bh, kb + 2);
        uint32_t stg = sb + bc * ASTG;
        bc  = (bc  == 2) ? 0 : bc  + 1;
        bl2 = (bl2 == 2) ? 0 : bl2 + 1;

        if (kb * 64 <= rowbase + 15) {
            // ---- S = Q K^T (plain fp16) ----
            float sacc[8][4];
            #pragma unroll
            for (int i = 0; i < 8; ++i)
                #pragma unroll
                for (int j = 0; j < 4; ++j) sacc[i][j] = 0.f;

            const uint32_t aK = stg + (uint32_t)((g >> 1) * 8 + r8) * 256;
            #pragma unroll
            for (int s = 0; s < 8; ++s) {
                uint32_t cB = ((uint32_t)(2 * s + (g & 1)) ^ (uint32_t)r8) << 4;
                #pragma unroll
                for (int ng = 0; ng < 4; ++ng) {
                    uint32_t k4[4];
                    ldm4(k4, aK + (uint32_t)ng * (16 * 256) + cB);
                    mma_f16(sacc[ng*2],   qh[s], &k4[0]);
                    mma_f16(sacc[ng*2+1], qh[s], &k4[2]);
                }
            }

            // ---- scale (+ causal mask on diagonal tiles), log2 domain ----
            if (kb >= 2 * qb) {
                #pragma unroll
                for (int nt = 0; nt < 8; ++nt)
                    #pragma unroll
                    for (int j = 0; j < 4; ++j) {
                        int col = kb * 64 + nt * 8 + lam * 2 + (j & 1);
                        int row = rowbase + ldiv + ((j >> 1) << 3);
                        sacc[nt][j] = (col <= row) ? sacc[nt][j] * C1 : -1e30f;
                    }
            } else {
                #pragma unroll
                for (int nt = 0; nt < 8; ++nt)
                    #pragma unroll
                    for (int j = 0; j < 4; ++j) sacc[nt][j] *= C1;
            }

            // ---- online softmax (rows r and r+8) ----
            float mr0 = -1e30f, mr1 = -1e30f;
            #pragma unroll
            for (int nt = 0; nt < 8; ++nt) {
                mr0 = fmaxf(mr0, fmaxf(sacc[nt][0], sacc[nt][1]));
                mr1 = fmaxf(mr1, fmaxf(sacc[nt][2], sacc[nt][3]));
            }
            mr0 = fmaxf(mr0, __shfl_xor_sync(0xffffffffu, mr0, 1));
            mr0 = fmaxf(mr0, __shfl_xor_sync(0xffffffffu, mr0, 2));
            mr1 = fmaxf(mr1, __shfl_xor_sync(0xffffffffu, mr1, 1));
            mr1 = fmaxf(mr1, __shfl_xor_sync(0xffffffffu, mr1, 2));
            float mn0 = fmaxf(m0, mr0), mn1 = fmaxf(m1, mr1);
            float al0 = ex2(m0 - mn0), al1 = ex2(m1 - mn1);
            m0 = mn0; m1 = mn1;
            float ls0 = 0.f, ls1 = 0.f;
            #pragma unroll
            for (int nt = 0; nt < 8; ++nt) {
                float p0 = ex2(sacc[nt][0] - mn0);
                float p1 = ex2(sacc[nt][1] - mn0);
                float p2 = ex2(sacc[nt][2] - mn1);
                float p3 = ex2(sacc[nt][3] - mn1);
                sacc[nt][0] = p0; sacc[nt][1] = p1;
                sacc[nt][2] = p2; sacc[nt][3] = p3;
                ls0 += p0 + p1;  ls1 += p2 + p3;
            }
            ls0 += __shfl_xor_sync(0xffffffffu, ls0, 1);
            ls0 += __shfl_xor_sync(0xffffffffu, ls0, 2);
            ls1 += __shfl_xor_sync(0xffffffffu, ls1, 1);
            ls1 += __shfl_xor_sync(0xffffffffu, ls1, 2);
            l0 = l0 * al0 + ls0;  l1 = l1 * al1 + ls1;
            #pragma unroll
            for (int i = 0; i < 16; ++i) {
                oacc[i][0] *= al0;  oacc[i][1] *= al0;
                oacc[i][2] *= al1;  oacc[i][3] *= al1;
            }

            // ---- O += P V (plain fp16 P) ----
            const uint32_t aV = stg + 16384 + (uint32_t)((g >> 1) * 8 + r8) * 128;
            #pragma unroll
            for (int s2 = 0; s2 < 4; ++s2) {
                uint32_t ph[4];
                ph[0] = packh(sacc[2*s2][0],   sacc[2*s2][1]);
                ph[1] = packh(sacc[2*s2][2],   sacc[2*s2][3]);
                ph[2] = packh(sacc[2*s2+1][0], sacc[2*s2+1][1]);
                ph[3] = packh(sacc[2*s2+1][2], sacc[2*s2+1][3]);
                uint32_t cV = ((uint32_t)(2 * s2 + (g & 1)) ^ (uint32_t)r8) << 4;
                #pragma unroll
                for (int ng = 0; ng < 8; ++ng) {
                    uint32_t v4[4];
                    ldm4(v4, aV + (uint32_t)ng * (16 * 128) + cV);
                    mma_f16(oacc[ng*2],   ph, &v4[0]);
                    mma_f16(oacc[ng*2+1], ph, &v4[2]);
                }
            }
        }
    }

    // ---- finalize: /l, write fp16 att [b,t,h*128+d] ----
    float inv0 = 1.f / l0, inv1 = 1.f / l1;
    const int b = bh >> 4, h = bh & 15;
    const int row0 = qb * 128 + w * 16 + ldiv;
    const size_t obase = ((size_t)b * NT + row0) * NC + h * ND;
    #pragma unroll
    for (int nt = 0; nt < 16; ++nt) {
        const int d = nt * 8 + lam * 2;
        *(uint32_t*)&g_attf[obase + d]          = packh(oacc[nt][0] * inv0, oacc[nt][1] * inv0);
        *(uint32_t*)&g_attf[obase + 8 * NC + d] = packh(oacc[nt][2] * inv1, oacc[nt][3] * inv1);
    }
}

// ---------------------------------------------------------------------------
// Launch
// ---------------------------------------------------------------------------
extern "C" void kernel_launch(void* const* d_in, const int* in_sizes, int n_in,
                              void* d_out, int out_size)
{
    const float* x    = (const float*)d_in[0];
    const float* Wqkv = (const float*)d_in[1];
    const float* bqkv = (const float*)d_in[2];
    const float* Wo   = (const float*)d_in[3];
    const float* bo   = (const float*)d_in[4];
    float* out = (float*)d_out;

    cudaFuncSetAttribute(gemm_fp16<0>,
                         cudaFuncAttributeMaxDynamicSharedMemorySize, GEMM_SMEM);
    cudaFuncSetAttribute(gemm_fp16<1>,
                         cudaFuncAttributeMaxDynamicSharedMemorySize, GEMM_SMEM);
    cudaFuncSetAttribute(attn_mma_kernel,
                         cudaFuncAttributeMaxDynamicSharedMemorySize, ATTN_SMEM);

    __half *xh, *Wh, *Woh, *attf;
    cudaGetSymbolAddress((void**)&xh,   g_xh);
    cudaGetSymbolAddress((void**)&Wh,   g_Wh);
    cudaGetSymbolAddress((void**)&Woh,  g_Woh);
    cudaGetSymbolAddress((void**)&attf, g_attf);

    // 1) conversions: x -> fp16 ; Wqkv^T, Wo^T -> fp16
    conv_f16_kernel<<<16384, 256>>>(x, xh, 4194304);
    transpose_conv_kernel<<<dim3(192, 64), dim3(32, 8)>>>(Wqkv, Wh, 2048, 6144);
    transpose_conv_kernel<<<dim3(64, 64),  dim3(32, 8)>>>(Wo, Woh, 2048, 2048);

    // 2) QKV GEMM with fused bias + RoPE + V-transpose -> g_qh/g_kh/g_vT fp16
    gemm_fp16<0><<<dim3(48, 64), 256, GEMM_SMEM>>>(xh, Wh, bqkv, nullptr);

    // 3) flash attention (plain fp16 mma.sync) -> g_attf
    attn_mma_kernel<<<dim3(16, 64), 256, ATTN_SMEM>>>();

    // 4) out = att @ Wo + bo (fp16 mma)
    gemm_fp16<1><<<dim3(16, 64), 256, GEMM_SMEM>>>(attf, Woh, bo, out);
}

// round 17
// speedup vs baseline: 1.1468x; 1.0049x over previous
#include <cuda_runtime.h>
#include <cuda_fp16.h>
#include <math.h>
#include <stdint.h>

// Problem dims (fixed by reference)
#define NB 4
#define NT 2048
#define NC 2048
#define NH 16
#define ND 128
#define NBH (NB*NH)          // 64
#define M1 (NB*NT)           // 8192
#define KDIM 2048

// ---------------------------------------------------------------------------
// Device scratch (allocation-free rule: __device__ globals)
// ---------------------------------------------------------------------------
__device__ __align__(256) __half g_xh[16777216];    // x fp16     [8192][2048]
__device__ __align__(256) __half g_Wh[12582912];    // Wqkv^T     [6144][2048]
__device__ __align__(256) __half g_Woh[4194304];    // Wo^T       [2048][2048]
__device__ __align__(256) __half g_attf[16777216];  // att fp16   [8192][2048]

__device__ __align__(256) __half g_qh[16777216];    // rope'd q fp16 [bh][t][d]
__device__ __align__(256) __half g_kh[16777216];    // rope'd k fp16 [bh][t][d]
__device__ __align__(256) __half g_vT[16777216];    // v^T fp16      [bh][d][t]

// ---------------------------------------------------------------------------
// PTX helpers (Ampere-class, valid under compute_103)
// ---------------------------------------------------------------------------
__device__ __forceinline__ uint32_t smem_u32(const void* p) {
    uint32_t a;
    asm("{ .reg .u64 t; cvta.to.shared.u64 t, %1; cvt.u32.u64 %0, t; }"
        : "=r"(a) : "l"(p));
    return a;
}
__device__ __forceinline__ void cp16(uint32_t s, const void* g) {
    asm volatile("cp.async.cg.shared.global [%0], [%1], 16;" :: "r"(s), "l"(g));
}
__device__ __forceinline__ void ldm4(uint32_t* r, uint32_t addr) {
    asm volatile("ldmatrix.sync.aligned.m8n8.x4.shared.b16 {%0,%1,%2,%3}, [%4];"
                 : "=r"(r[0]), "=r"(r[1]), "=r"(r[2]), "=r"(r[3]) : "r"(addr));
}
__device__ __forceinline__ void mma_f16(float* c, const uint32_t* a, const uint32_t* b) {
    asm volatile(
        "mma.sync.aligned.m16n8k16.row.col.f32.f16.f16.f32 "
        "{%0,%1,%2,%3}, {%4,%5,%6,%7}, {%8,%9}, {%0,%1,%2,%3};"
        : "+f"(c[0]), "+f"(c[1]), "+f"(c[2]), "+f"(c[3])
        : "r"(a[0]), "r"(a[1]), "r"(a[2]), "r"(a[3]), "r"(b[0]), "r"(b[1]));
}
__device__ __forceinline__ float ex2(float x) {
    float y; asm("ex2.approx.f32 %0, %1;" : "=f"(y) : "f"(x)); return y;
}
__device__ __forceinline__ uint32_t packh(float x, float y) {
    __half2 h = __floats2half2_rn(x, y);
    return *(uint32_t*)&h;
}

// ---------------------------------------------------------------------------
// Plain fp16 mma.sync GEMM: C[M,N] = A[M,K] @ B^T
// BM=128 BN=128 BK=64, 8 warps (2x4). 3-stage, 1 sync/stage, 96KB, 2 CTAs/SM.
// EPI==0: QKV epilogue — RoPE (q,k) / transpose (v) fused, fp16 outputs.
// EPI==1: bias + row-major fp32 store.
// ---------------------------------------------------------------------------
#define BK 64
#define NKCH (KDIM/BK)       // 32
#define STG_SZ 32768
#define GEMM_SMEM (3*STG_SZ) // 98304  (>= 128*129*4 = 66048 for epilogue tile)

__device__ __forceinline__ void load_stage32(
    uint32_t stg, int t, int koff,
    const __half* pA, const __half* pB)
{
    #pragma unroll
    for (int i = 0; i < 4; ++i) {
        int idx = t + i * 256;
        int r = idx >> 3, ci = idx & 7;
        uint32_t so = stg + r * 128 + ((ci ^ (r & 7)) << 4);
        size_t go = (size_t)r * KDIM + koff + ci * 8;
        cp16(so,          pA + go);
        cp16(so + 16384,  pB + go);
    }
    asm volatile("cp.async.commit_group;" ::: "memory");
}

__device__ __forceinline__ void compute_stage(
    uint32_t stg, int wm, int wn, int lane, float acc[4][4][4])
{
    const int r = lane & 7, g = lane >> 3;
    const uint32_t rx = (uint32_t)r << 4;
    const uint32_t baseA = stg + (uint32_t)(wm * 64 + (g & 1) * 8 + r) * 128;
    const uint32_t hA4   = (uint32_t)(g >> 1) << 4;
    const uint32_t baseB = stg + 16384 + (uint32_t)(wn * 32 + (g >> 1) * 8 + r) * 128;
    const uint32_t hB4   = (uint32_t)(g & 1) << 4;

    #pragma unroll
    for (int s = 0; s < 4; ++s) {
        const uint32_t offA = (((uint32_t)s << 5) | hA4) ^ rx;
        const uint32_t offB = (((uint32_t)s << 5) | hB4) ^ rx;
        uint32_t ah[4][4], bh[2][4];
        #pragma unroll
        for (int i = 0; i < 4; ++i)
            ldm4(ah[i], baseA + i * 2048 + offA);
        #pragma unroll
        for (int j = 0; j < 2; ++j)
            ldm4(bh[j], baseB + j * 2048 + offB);
        #pragma unroll
        for (int i = 0; i < 4; ++i)
            #pragma unroll
            for (int q = 0; q < 4; ++q)
                mma_f16(acc[i][q], ah[i], &bh[q >> 1][(q & 1) * 2]);
    }
}

template<int EPI>
__global__ __launch_bounds__(256, 2)
void gemm_fp16(const __half* __restrict__ A, const __half* __restrict__ B,
               const float* __restrict__ bias, float* __restrict__ C)
{
    extern __shared__ __align__(1024) char smbuf[];
    uint32_t sb = smem_u32(smbuf);
    const int t    = threadIdx.x;
    const int lane = t & 31, wid = t >> 5;
    const int wm   = wid >> 2, wn = wid & 3;
    const int m0   = blockIdx.y * 128;
    const int n0   = blockIdx.x * 128;

    float acc[4][4][4];
    #pragma unroll
    for (int i = 0; i < 4; ++i)
        #pragma unroll
        for (int q = 0; q < 4; ++q)
            #pragma unroll
            for (int k = 0; k < 4; ++k) acc[i][q][k] = 0.f;

    const __half* pA = A + (size_t)m0 * KDIM;
    const __half* pB = B + (size_t)n0 * KDIM;

    load_stage32(sb,          t, 0,  pA, pB);
    load_stage32(sb + STG_SZ, t, BK, pA, pB);

    int bc = 0, bl2 = 2;
    #pragma unroll 1
    for (int kt = 0; kt < NKCH; ++kt) {
        if (kt == NKCH - 1) asm volatile("cp.async.wait_group 0;" ::: "memory");
        else                asm volatile("cp.async.wait_group 1;" ::: "memory");
        __syncthreads();
        if (kt + 2 < NKCH)
            load_stage32(sb + bl2 * STG_SZ, t, (kt + 2) * BK, pA, pB);
        compute_stage(sb + bc * STG_SZ, wm, wn, lane, acc);
        bc  = (bc  == 2) ? 0 : bc  + 1;
        bl2 = (bl2 == 2) ? 0 : bl2 + 1;
    }

    const int mr  = (lane >> 2);
    const int nc0 = (lane & 3) * 2;
    if (EPI == 0) {
        // ---- fused QKV epilogue: stage biased fp32 tile in smem ----
        float* smf = (float*)smbuf;
        __syncthreads();
        #pragma unroll
        for (int i = 0; i < 4; ++i) {
            const int ml = wm * 64 + i * 16 + mr;
            #pragma unroll
            for (int q = 0; q < 4; ++q) {
                const int dl = wn * 32 + q * 8 + nc0;
                float2 bs = *(const float2*)&bias[n0 + dl];
                smf[ml * 129 + dl]           = acc[i][q][0] + bs.x;
                smf[ml * 129 + dl + 1]       = acc[i][q][1] + bs.y;
                smf[(ml + 8) * 129 + dl]     = acc[i][q][2] + bs.x;
                smf[(ml + 8) * 129 + dl + 1] = acc[i][q][3] + bs.y;
            }
        }
        __syncthreads();
        const int which = n0 >> 11;          // 0=q 1=k 2=v
        const int h     = (n0 >> 7) & 15;
        const int b     = m0 >> 11;
        const int tq0   = m0 & 2047;
        const int bh    = b * 16 + h;
        if (which == 2) {
            // transpose: v[t][d] -> g_vT[bh][d][t] (fp16)
            __half* dv = (__half*)g_vT + (size_t)bh * ND * NT + tq0;
            #pragma unroll
            for (int it = 0; it < 32; ++it) {
                int idx = t + it * 256;
                int d = idx >> 6, m2 = (idx & 63) * 2;
                float f0 = smf[m2 * 129 + d];
                float f1 = smf[(m2 + 1) * 129 + d];
                *(uint32_t*)&dv[(size_t)d * NT + m2] = packh(f0, f1);
            }
        } else {
            // RoPE + fp16. theta = 10000^(-f/64) = exp2(-f*log2(1e4)/64)
            const float K2 = -0.20762050593046015f;  // -log2(10000)/64
            __half* dq = ((which == 0) ? (__half*)g_qh : (__half*)g_kh)
                       + ((size_t)bh * NT + tq0) * ND;
            #pragma unroll
            for (int it = 0; it < 16; ++it) {
                int idx = t + it * 256;
                int row = idx >> 5, fi = idx & 31;
                const float* rp = smf + row * 129;
                float x1a = rp[2 * fi],      x1b = rp[2 * fi + 1];
                float x2a = rp[2 * fi + 64], x2b = rp[2 * fi + 65];
                float tpos = (float)(tq0 + row);
                float fa = 2.0f * fi;
                float th0 = exp2f(fa * K2);
                float s0, c0; sincosf(tpos * th0, &s0, &c0);
                float th1 = exp2f((fa + 1.0f) * K2);
                float s1, c1; sincosf(tpos * th1, &s1, &c1);
                float y1a = x1a * c0 - x2a * s0, y2a = x1a * s0 + x2a * c0;
                float y1b = x1b * c1 - x2b * s1, y2b = x1b * s1 + x2b * c1;
                *(uint32_t*)&dq[(size_t)row * ND + 2 * fi]      = packh(y1a, y1b);
                *(uint32_t*)&dq[(size_t)row * ND + 2 * fi + 64] = packh(y2a, y2b);
            }
        }
    } else {
        #pragma unroll
        for (int i = 0; i < 4; ++i) {
            const int m = m0 + wm * 64 + i * 16 + mr;
            #pragma unroll
            for (int q = 0; q < 4; ++q) {
                const int n = n0 + wn * 32 + q * 8 + nc0;
                float2 bs = *(const float2*)&bias[n];
                float2 v0, v1;
                v0.x = acc[i][q][0] + bs.x;  v0.y = acc[i][q][1] + bs.y;
                v1.x = acc[i][q][2] + bs.x;  v1.y = acc[i][q][3] + bs.y;
                *(float2*)&C[(size_t)m * NC + n]       = v0;
                *(float2*)&C[(size_t)(m + 8) * NC + n] = v1;
            }
        }
    }
}

// ---------------------------------------------------------------------------
// fp32 -> fp16 convert (x input)
// ---------------------------------------------------------------------------
__global__ void conv_f16_kernel(const float* __restrict__ in,
                                __half* __restrict__ out, int n4)
{
    int i = blockIdx.x * blockDim.x + threadIdx.x;
    if (i >= n4) return;
    float4 v = ((const float4*)in)[i];
    uint32_t* op = (uint32_t*)out;
    op[2 * i]     = packh(v.x, v.y);
    op[2 * i + 1] = packh(v.z, v.w);
}

// ---------------------------------------------------------------------------
// fp32 [K][N] -> transposed fp16 [N][K]  (weights)
// ---------------------------------------------------------------------------
__global__ void transpose_conv_kernel(const float* __restrict__ in,
                                      __half* __restrict__ out,
                                      int K, int N)
{
    __shared__ float tile[32][33];
    const int n0 = blockIdx.x * 32, k0 = blockIdx.y * 32;
    const int tx = threadIdx.x, ty = threadIdx.y;
    #pragma unroll
    for (int i = 0; i < 32; i += 8)
        tile[ty + i][tx] = in[(size_t)(k0 + ty + i) * N + n0 + tx];
    __syncthreads();
    #pragma unroll
    for (int i = 0; i < 32; i += 8) {
        size_t o = (size_t)(n0 + ty + i) * K + k0 + tx;
        out[o] = __float2half_rn(tile[tx][ty + i]);
    }
}

// ---------------------------------------------------------------------------
// Flash attention, plain fp16 mma.sync (R11 proven config).
// BQ=128, BK=64, 8 warps. 3 x 32KB K/V stages + Q 32KB = 128KB.
// ---------------------------------------------------------------------------
#define ASTG 32768
#define ATTN_SMEM (3*ASTG + 32768)   // 131072

__device__ __forceinline__ void attn_load_kv(uint32_t stg, int t, int bh, int kb)
{
    const size_t koff = ((size_t)bh * NT + kb * 64) * ND;
    #pragma unroll
    for (int i = 0; i < 4; ++i) {
        int idx = t + i * 256;
        int r = idx >> 4, c = idx & 15;
        uint32_t dst = stg + r * 256 + ((c ^ (r & 7)) << 4);
        cp16(dst, (const __half*)g_kh + koff + (size_t)r * ND + c * 8);
    }
    const size_t voff = (size_t)bh * ND * NT + kb * 64;
    #pragma unroll
    for (int i = 0; i < 4; ++i) {
        int idx = t + i * 256;
        int r = idx >> 3, c = idx & 7;
        uint32_t dst = stg + 16384 + r * 128 + ((c ^ (r & 7)) << 4);
        cp16(dst, (const __half*)g_vT + voff + (size_t)r * NT + c * 8);
    }
    asm volatile("cp.async.commit_group;" ::: "memory");
}

__global__ __launch_bounds__(256, 1)
void attn_mma_kernel()
{
    extern __shared__ __align__(1024) char abuf[];
    uint32_t sb = smem_u32(abuf);
    const int t = threadIdx.x, lane = t & 31, w = t >> 5;
    const int lam = lane & 3, ldiv = lane >> 2;
    const int g = lane >> 3, r8 = lane & 7;
    const int qb = 15 - (int)blockIdx.x;   // heavy q-blocks first
    const int bh = blockIdx.y;
    const float C1 = 0.08838834764831845f * 1.4426950408889634f; // scale*log2e

    // Q tile (128 x 128) plain fp16
    const uint32_t qreg = sb + 3 * ASTG;
    const size_t qoff = ((size_t)bh * NT + qb * 128) * ND;
    #pragma unroll
    for (int i = 0; i < 8; ++i) {
        int idx = t + i * 256;
        int r = idx >> 4, c = idx & 15;
        uint32_t dst = qreg + r * 256 + ((c ^ (r & 7)) << 4);
        cp16(dst, (const __half*)g_qh + qoff + (size_t)r * ND + c * 8);
    }
    asm volatile("cp.async.commit_group;" ::: "memory");   // group: Q
    const int nkt = 2 * qb + 2;
    attn_load_kv(sb,        t, bh, 0);
    attn_load_kv(sb + ASTG, t, bh, 1);

    asm volatile("cp.async.wait_group 2;" ::: "memory");
    __syncthreads();
    uint32_t qh[8][4];
    {
        const uint32_t aQ = qreg + (uint32_t)(w * 16 + (g & 1) * 8 + r8) * 256;
        #pragma unroll
        for (int s = 0; s < 8; ++s) {
            uint32_t cA = ((uint32_t)(2 * s + (g >> 1)) ^ (uint32_t)r8) << 4;
            ldm4(qh[s], aQ + cA);
        }
    }

    float oacc[16][4];
    #pragma unroll
    for (int i = 0; i < 16; ++i)
        #pragma unroll
        for (int j = 0; j < 4; ++j) oacc[i][j] = 0.f;
    float m0 = -INFINITY, m1 = -INFINITY, l0 = 0.f, l1 = 0.f;

    const int rowbase = qb * 128 + w * 16;

    int bc = 0, bl2 = 2;
    #pragma unroll 1
    for (int kb = 0; kb < nkt; ++kb) {
        if (kb == nkt - 1) asm volatile("cp.async.wait_group 0;" ::: "memory");
        else               asm volatile("cp.async.wait_group 1;" ::: "memory");
        __syncthreads();
        if (kb + 2 < nkt) attn_load_kv(sb + bl2 * ASTG, t, bh, kb + 2);
        uint32_t stg = sb + bc * ASTG;
        bc  = (bc  == 2) ? 0 : bc  + 1;
        bl2 = (bl2 == 2) ? 0 : bl2 + 1;

        if (kb * 64 <= rowbase + 15) {
            // ---- S = Q K^T (plain fp16) ----
            float sacc[8][4];
            #pragma unroll
            for (int i = 0; i < 8; ++i)
                #pragma unroll
                for (int j = 0; j < 4; ++j) sacc[i][j] = 0.f;

            const uint32_t aK = stg + (uint32_t)((g >> 1) * 8 + r8) * 256;
            #pragma unroll
            for (int s = 0; s < 8; ++s) {
                uint32_t cB = ((uint32_t)(2 * s + (g & 1)) ^ (uint32_t)r8) << 4;
                #pragma unroll
                for (int ng = 0; ng < 4; ++ng) {
                    uint32_t k4[4];
                    ldm4(k4, aK + (uint32_t)ng * (16 * 256) + cB);
                    mma_f16(sacc[ng*2],   qh[s], &k4[0]);
                    mma_f16(sacc[ng*2+1], qh[s], &k4[2]);
                }
            }

            // ---- scale (+ causal mask on diagonal tiles), log2 domain ----
            if (kb >= 2 * qb) {
                #pragma unroll
                for (int nt = 0; nt < 8; ++nt)
                    #pragma unroll
                    for (int j = 0; j < 4; ++j) {
                        int col = kb * 64 + nt * 8 + lam * 2 + (j & 1);
                        int row = rowbase + ldiv + ((j >> 1) << 3);
                        sacc[nt][j] = (col <= row) ? sacc[nt][j] * C1 : -1e30f;
                    }
            } else {
                #pragma unroll
                for (int nt = 0; nt < 8; ++nt)
                    #pragma unroll
                    for (int j = 0; j < 4; ++j) sacc[nt][j] *= C1;
            }

            // ---- online softmax (rows r and r+8) ----
            float mr0 = -1e30f, mr1 = -1e30f;
            #pragma unroll
            for (int nt = 0; nt < 8; ++nt) {
                mr0 = fmaxf(mr0, fmaxf(sacc[nt][0], sacc[nt][1]));
                mr1 = fmaxf(mr1, fmaxf(sacc[nt][2], sacc[nt][3]));
            }
            mr0 = fmaxf(mr0, __shfl_xor_sync(0xffffffffu, mr0, 1));
            mr0 = fmaxf(mr0, __shfl_xor_sync(0xffffffffu, mr0, 2));
            mr1 = fmaxf(mr1, __shfl_xor_sync(0xffffffffu, mr1, 1));
            mr1 = fmaxf(mr1, __shfl_xor_sync(0xffffffffu, mr1, 2));
            float mn0 = fmaxf(m0, mr0), mn1 = fmaxf(m1, mr1);
            float al0 = ex2(m0 - mn0), al1 = ex2(m1 - mn1);
            m0 = mn0; m1 = mn1;
            float ls0 = 0.f, ls1 = 0.f;
            #pragma unroll
            for (int nt = 0; nt < 8; ++nt) {
                float p0 = ex2(sacc[nt][0] - mn0);
                float p1 = ex2(sacc[nt][1] - mn0);
                float p2 = ex2(sacc[nt][2] - mn1);
                float p3 = ex2(sacc[nt][3] - mn1);
                sacc[nt][0] = p0; sacc[nt][1] = p1;
                sacc[nt][2] = p2; sacc[nt][3] = p3;
                ls0 += p0 + p1;  ls1 += p2 + p3;
            }
            ls0 += __shfl_xor_sync(0xffffffffu, ls0, 1);
            ls0 += __shfl_xor_sync(0xffffffffu, ls0, 2);
            ls1 += __shfl_xor_sync(0xffffffffu, ls1, 1);
            ls1 += __shfl_xor_sync(0xffffffffu, ls1, 2);
            l0 = l0 * al0 + ls0;  l1 = l1 * al1 + ls1;
            #pragma unroll
            for (int i = 0; i < 16; ++i) {
                oacc[i][0] *= al0;  oacc[i][1] *= al0;
                oacc[i][2] *= al1;  oacc[i][3] *= al1;
            }

            // ---- O += P V (plain fp16 P) ----
            const uint32_t aV = stg + 16384 + (uint32_t)((g >> 1) * 8 + r8) * 128;
            #pragma unroll
            for (int s2 = 0; s2 < 4; ++s2) {
                uint32_t ph[4];
                ph[0] = packh(sacc[2*s2][0],   sacc[2*s2][1]);
                ph[1] = packh(sacc[2*s2][2],   sacc[2*s2][3]);
                ph[2] = packh(sacc[2*s2+1][0], sacc[2*s2+1][1]);
                ph[3] = packh(sacc[2*s2+1][2], sacc[2*s2+1][3]);
                uint32_t cV = ((uint32_t)(2 * s2 + (g & 1)) ^ (uint32_t)r8) << 4;
                #pragma unroll
                for (int ng = 0; ng < 8; ++ng) {
                    uint32_t v4[4];
                    ldm4(v4, aV + (uint32_t)ng * (16 * 128) + cV);
                    mma_f16(oacc[ng*2],   ph, &v4[0]);
                    mma_f16(oacc[ng*2+1], ph, &v4[2]);
                }
            }
        }
    }

    // ---- finalize: /l, write fp16 att [b,t,h*128+d] ----
    float inv0 = 1.f / l0, inv1 = 1.f / l1;
    const int b = bh >> 4, h = bh & 15;
    const int row0 = qb * 128 + w * 16 + ldiv;
    const size_t obase = ((size_t)b * NT + row0) * NC + h * ND;
    #pragma unroll
    for (int nt = 0; nt < 16; ++nt) {
        const int d = nt * 8 + lam * 2;
        *(uint32_t*)&g_attf[obase + d]          = packh(oacc[nt][0] * inv0, oacc[nt][1] * inv0);
        *(uint32_t*)&g_attf[obase + 8 * NC + d] = packh(oacc[nt][2] * inv1, oacc[nt][3] * inv1);
    }
}

// ---------------------------------------------------------------------------
// Launch — fork/join streams so prep kernels overlap (graph-capture legal)
// ---------------------------------------------------------------------------
extern "C" void kernel_launch(void* const* d_in, const int* in_sizes, int n_in,
                              void* d_out, int out_size)
{
    const float* x    = (const float*)d_in[0];
    const float* Wqkv = (const float*)d_in[1];
    const float* bqkv = (const float*)d_in[2];
    const float* Wo   = (const float*)d_in[3];
    const float* bo   = (const float*)d_in[4];
    float* out = (float*)d_out;

    static cudaStream_t s1 = nullptr, s2 = nullptr;
    static cudaEvent_t ef1, ef2, ej1, ej2;
    if (!s1) {
        cudaStreamCreateWithFlags(&s1, cudaStreamNonBlocking);
        cudaStreamCreateWithFlags(&s2, cudaStreamNonBlocking);
        cudaEventCreateWithFlags(&ef1, cudaEventDisableTiming);
        cudaEventCreateWithFlags(&ef2, cudaEventDisableTiming);
        cudaEventCreateWithFlags(&ej1, cudaEventDisableTiming);
        cudaEventCreateWithFlags(&ej2, cudaEventDisableTiming);

        cudaFuncSetAttribute(gemm_fp16<0>,
                             cudaFuncAttributeMaxDynamicSharedMemorySize, GEMM_SMEM);
        cudaFuncSetAttribute(gemm_fp16<1>,
                             cudaFuncAttributeMaxDynamicSharedMemorySize, GEMM_SMEM);
        cudaFuncSetAttribute(attn_mma_kernel,
                             cudaFuncAttributeMaxDynamicSharedMemorySize, ATTN_SMEM);
    }

    __half *xh, *Wh, *Woh, *attf;
    cudaGetSymbolAddress((void**)&xh,   g_xh);
    cudaGetSymbolAddress((void**)&Wh,   g_Wh);
    cudaGetSymbolAddress((void**)&Woh,  g_Woh);
    cudaGetSymbolAddress((void**)&attf, g_attf);

    // Fork: s1 does Wqkv transpose (needed by gemm1); s2 does Wo transpose
    // (needed only by gemm2). Main stream does x conversion.
    cudaEventRecord(ef1, 0);
    cudaStreamWaitEvent(s1, ef1, 0);
    cudaEventRecord(ef2, 0);
    cudaStreamWaitEvent(s2, ef2, 0);

    conv_f16_kernel<<<16384, 256>>>(x, xh, 4194304);
    transpose_conv_kernel<<<dim3(192, 64), dim3(32, 8), 0, s1>>>(Wqkv, Wh, 2048, 6144);
    transpose_conv_kernel<<<dim3(64, 64),  dim3(32, 8), 0, s2>>>(Wo, Woh, 2048, 2048);

    // Join s1 before gemm1
    cudaEventRecord(ej1, s1);
    cudaStreamWaitEvent(0, ej1, 0);

    // QKV GEMM with fused bias + RoPE + V-transpose -> g_qh/g_kh/g_vT fp16
    gemm_fp16<0><<<dim3(48, 64), 256, GEMM_SMEM>>>(xh, Wh, bqkv, nullptr);

    // flash attention (plain fp16 mma.sync) -> g_attf
    attn_mma_kernel<<<dim3(16, 64), 256, ATTN_SMEM>>>();

    // Join s2 before gemm2 (Wo transpose overlapped with gemm1+attention)
    cudaEventRecord(ej2, s2);
    cudaStreamWaitEvent(0, ej2, 0);

    // out = att @ Wo + bo (fp16 mma)
    gemm_fp16<1><<<dim3(16, 64), 256, GEMM_SMEM>>>(attf, Woh, bo, out);
}